// round 12
// baseline (speedup 1.0000x reference)
#include <cuda_runtime.h>
#include <cuda_bf16.h>
#include <cuda_fp16.h>
#include <math.h>
#include <stdint.h>

// Problem constants
#define B_   4
#define T_   2048
#define C_   2048
#define H_   16
#define D_   128
#define BH_  (B_ * H_)        // 64
#define M_   (B_ * T_)        // 8192
#define N3_  (3 * C_)         // 6144

// ============================ helpers ======================================
__device__ __forceinline__ uint32_t smem_u32(const void* p) {
    uint32_t a;
    asm("{ .reg .u64 t; cvta.to.shared.u64 t, %1; cvt.u32.u64 %0, t; }"
        : "=r"(a) : "l"(p));
    return a;
}
#define CP_ASYNC16(saddr, gptr) \
    asm volatile("cp.async.cg.shared.global [%0], [%1], 16;" \
                 :: "r"(saddr), "l"(gptr) : "memory")
#define CP_COMMIT() asm volatile("cp.async.commit_group;" ::: "memory")
#define CP_WAIT_GROUP(n) asm volatile("cp.async.wait_group %0;" :: "n"(n) : "memory")

#define LDMATRIX_X4(r0, r1, r2, r3, addr) \
    asm volatile("ldmatrix.sync.aligned.m8n8.x4.shared.b16 {%0,%1,%2,%3}, [%4];" \
                 : "=r"(r0), "=r"(r1), "=r"(r2), "=r"(r3) : "r"(addr))
#define LDMATRIX_X4_T(r0, r1, r2, r3, addr) \
    asm volatile("ldmatrix.sync.aligned.m8n8.x4.trans.shared.b16 {%0,%1,%2,%3}, [%4];" \
                 : "=r"(r0), "=r"(r1), "=r"(r2), "=r"(r3) : "r"(addr))
#define MMA_FP16(c, a, b) \
    asm volatile("mma.sync.aligned.m16n8k16.row.col.f32.f16.f16.f32 " \
                 "{%0,%1,%2,%3}, {%4,%5,%6,%7}, {%8,%9}, {%0,%1,%2,%3};" \
                 : "+f"((c)[0]), "+f"((c)[1]), "+f"((c)[2]), "+f"((c)[3]) \
                 : "r"((a)[0]), "r"((a)[1]), "r"((a)[2]), "r"((a)[3]), \
                   "r"((b)[0]), "r"((b)[1]))

// ---------------- scratch (device globals; no allocation allowed) ----------
__device__ __half g_qkv16[M_ * N3_];       // [8192, 6144] fp16 (QKV pre-rope)
__device__ float g_cos[T_ * 64];
__device__ float g_sin[T_ * 64];
__device__ __half gx_s[M_ * C_];           // activations [M,K]
__device__ __half gcx_s[M_ * C_];          // ctx [M,K]
__device__ __half gwq[N3_ * C_];           // W_qkv^T [N,K]
__device__ __half gwp[C_ * C_];            // W_proj^T [N,K]
__device__ __half gq_s[BH_ * T_ * D_];
__device__ __half gk_s[BH_ * T_ * D_];
__device__ __half gv_s[BH_ * T_ * D_];

// ---------------------------------------------------------------------------
// round fp32 -> fp16, elementwise (vectorized by 4)
// ---------------------------------------------------------------------------
__global__ void __launch_bounds__(256) round_kernel(
    const float* __restrict__ in, __half* __restrict__ out16, int n4)
{
    int i = blockIdx.x * 256 + threadIdx.x;
    if (i >= n4) return;
    float4 v = ((const float4*)in)[i];
    __half2* hp = (__half2*)out16;
    hp[i * 2 + 0] = __floats2half2_rn(v.x, v.y);
    hp[i * 2 + 1] = __floats2half2_rn(v.z, v.w);
}

// ---------------------------------------------------------------------------
// transpose + round: W[K,N] fp32 -> Wh[N,K] fp16
// ---------------------------------------------------------------------------
__global__ void __launch_bounds__(256) transpose_h_kernel(
    const float* __restrict__ W, __half* __restrict__ Th, int K, int N)
{
    __shared__ float t[32][33];
    int bn = blockIdx.x * 32;
    int bk = blockIdx.y * 32;
    int x = threadIdx.x, y = threadIdx.y;       // 32 x 8
#pragma unroll
    for (int i = 0; i < 32; i += 8)
        t[y + i][x] = W[(size_t)(bk + y + i) * N + bn + x];
    __syncthreads();
#pragma unroll
    for (int i = 0; i < 32; i += 8) {
        float v = t[x][y + i];                  // = W[bk+x][bn+y+i]
        Th[(size_t)(bn + y + i) * K + bk + x] = __float2half_rn(v);
    }
}

// ---------------------------------------------------------------------------
// Persistent HMMA GEMM: C[M,N] = A[M,K] @ B[N,K]^T, fp16 x fp16, fp32 accum.
// Grid = 296 CTAs (2/SM), each loops over 128x128 tiles. BK=64, 3-stage
// cp.async (wait_group 1), one commit per iteration (empty commits keep the
// group count aligned across tiles).
// OUT16=0: fp32 epilogue (+bias). OUT16=1: fp16 epilogue (no bias).
// ---------------------------------------------------------------------------
#define STG_BYTES 32768              // A 16K + B 16K
#define OFF_A 0
#define OFF_B 16384
#define GEMM_SMEM (3 * STG_BYTES)    // 96 KB
#define GEMM_GRID 296

__device__ __forceinline__ void gemm_load_stage(
    uint32_t sb, int stage,
    const __half* __restrict__ A, const __half* __restrict__ Bh,
    int row0, int col0, int kb, int K, int tid)
{
    uint32_t st = sb + stage * STG_BYTES;
    const int k0 = kb * 64;
#pragma unroll
    for (int u = 0; u < 4; u++) {
        int idx = u * 256 + tid;                 // 1024 16B chunks per operand
        int r = idx >> 3, c = idx & 7;
        uint32_t sw = (uint32_t)(r * 128 + ((c ^ (r & 7)) << 4));
        size_t ga = (size_t)(row0 + r) * K + k0 + c * 8;
        size_t gb = (size_t)(col0 + r) * K + k0 + c * 8;
        CP_ASYNC16(st + OFF_A + sw, A + ga);
        CP_ASYNC16(st + OFF_B + sw, Bh + gb);
    }
}

template<int OUT16>
__global__ void __launch_bounds__(256, 2) gemm_mma_kernel(
    const __half* __restrict__ A, const __half* __restrict__ Bh,
    float* __restrict__ Cout, __half* __restrict__ Cout16,
    const float* __restrict__ bias, int N, int K, int ntx, int ntiles)
{
    extern __shared__ __align__(1024) char smem[];
    const uint32_t sb = smem_u32(smem);
    const int tid = threadIdx.x;
    const int wid = tid >> 5, lane = tid & 31;
    const int wr = wid >> 2, wc = wid & 3;       // warp grid 2 x 4
    const int NK = K / 64;

    const int a_row = wr * 64 + (lane & 15);
    const int a_cg  = (lane >> 4);
    const int b_row = wc * 32 + (lane & 7) + ((lane >> 4) << 3);
    const int b_cg  = ((lane >> 3) & 1);
    const int er = lane >> 2;
    const int ec = (lane & 3) * 2;

    for (int tile = blockIdx.x; tile < ntiles; tile += GEMM_GRID) {
        const int col0 = (tile % ntx) * 128;
        const int row0 = (tile / ntx) * 128;

        float acc[4][4][4];
#pragma unroll
        for (int i = 0; i < 4; i++)
#pragma unroll
            for (int j = 0; j < 4; j++)
#pragma unroll
                for (int k = 0; k < 4; k++) acc[i][j][k] = 0.f;

        gemm_load_stage(sb, 0, A, Bh, row0, col0, 0, K, tid);
        CP_COMMIT();
        gemm_load_stage(sb, 1, A, Bh, row0, col0, 1, K, tid);
        CP_COMMIT();

        int slot = 0, nslot = 2;
        for (int kb = 0; kb < NK; kb++) {
            CP_WAIT_GROUP(1);
            __syncthreads();
            if (kb + 2 < NK)
                gemm_load_stage(sb, nslot, A, Bh, row0, col0, kb + 2, K, tid);
            CP_COMMIT();

            uint32_t st = sb + slot * STG_BYTES;
#pragma unroll
            for (int ks = 0; ks < 4; ks++) {
                uint32_t af[4][4], bf[4][2];
#pragma unroll
                for (int mt = 0; mt < 4; mt++) {
                    int r = a_row + mt * 16;
                    int c = ks * 2 + a_cg;
                    uint32_t ad = st + (uint32_t)(r * 128 + ((c ^ (r & 7)) << 4));
                    LDMATRIX_X4(af[mt][0], af[mt][1], af[mt][2], af[mt][3], ad + OFF_A);
                }
#pragma unroll
                for (int ntp = 0; ntp < 2; ntp++) {
                    int n = b_row + ntp * 16;
                    int c = ks * 2 + b_cg;
                    uint32_t bd = st + (uint32_t)(n * 128 + ((c ^ (n & 7)) << 4));
                    LDMATRIX_X4(bf[2 * ntp][0], bf[2 * ntp][1],
                                bf[2 * ntp + 1][0], bf[2 * ntp + 1][1], bd + OFF_B);
                }
#pragma unroll
                for (int mt = 0; mt < 4; mt++)
#pragma unroll
                    for (int nt = 0; nt < 4; nt++)
                        MMA_FP16(acc[mt][nt], af[mt], bf[nt]);
            }
            slot = (slot == 2) ? 0 : slot + 1;
            nslot = (nslot == 2) ? 0 : nslot + 1;
        }

        // Epilogue (regs -> gmem, no smem)
#pragma unroll
        for (int mt = 0; mt < 4; mt++) {
            int row = row0 + wr * 64 + mt * 16 + er;
#pragma unroll
            for (int nt = 0; nt < 4; nt++) {
                int col = col0 + wc * 32 + nt * 8 + ec;
                if (OUT16) {
                    *(__half2*)&Cout16[(size_t)row * N + col] =
                        __floats2half2_rn(acc[mt][nt][0], acc[mt][nt][1]);
                    *(__half2*)&Cout16[(size_t)(row + 8) * N + col] =
                        __floats2half2_rn(acc[mt][nt][2], acc[mt][nt][3]);
                } else {
                    float b0 = 0.f, b1 = 0.f;
                    if (bias) { b0 = bias[col]; b1 = bias[col + 1]; }
                    float2 v0, v1;
                    v0.x = acc[mt][nt][0] + b0; v0.y = acc[mt][nt][1] + b1;
                    v1.x = acc[mt][nt][2] + b0; v1.y = acc[mt][nt][3] + b1;
                    *(float2*)&Cout[(size_t)row * N + col] = v0;
                    *(float2*)&Cout[(size_t)(row + 8) * N + col] = v1;
                }
            }
        }
        // All warps finished reading current stages before next tile's loads
        __syncthreads();
    }
}

// ---------------------------------------------------------------------------
// RoPE table
// ---------------------------------------------------------------------------
__global__ void rope_table_kernel()
{
    int g = blockIdx.x * blockDim.x + threadIdx.x;
    if (g >= T_ * 64) return;
    int t = g >> 6, i = g & 63;
    double invf = pow(10000.0, -(double)i / 64.0);
    float  angf = (float)t * (float)invf;
    double ang  = (double)angf;
    g_cos[g] = (float)cos(ang);
    g_sin[g] = (float)sin(ang);
}

// ---------------------------------------------------------------------------
// RoPE (vectorized 8 halves/thread): g_qkv16[B,T,3C] -> q/k/v fp16 [BH,T,D]
// ---------------------------------------------------------------------------
__global__ void __launch_bounds__(256) rope_kernel()
{
    int g = blockIdx.x * 256 + threadIdx.x;     // BH*T*16 threads
    int dv = (g & 15) * 8;                      // 0,8,...,120
    int t  = (g >> 4) & 2047;
    int bh = g >> 15;
    int b  = bh >> 4, h = bh & 15;

    size_t src  = ((size_t)(b * T_ + t)) * N3_ + h * D_ + dv;
    size_t srcp = src - dv + (dv ^ 64);

    uint4 qa = *(const uint4*)&g_qkv16[src];
    uint4 qb = *(const uint4*)&g_qkv16[srcp];
    uint4 ka = *(const uint4*)&g_qkv16[src + C_];
    uint4 kb = *(const uint4*)&g_qkv16[srcp + C_];
    uint4 va = *(const uint4*)&g_qkv16[src + 2 * C_];

    float sgn = (dv < 64) ? -1.f : 1.f;
    int i0 = dv & 63;
    const float* ct = g_cos + t * 64 + i0;
    const float* st = g_sin + t * 64 + i0;

    uint4 qo, ko;
    const uint32_t* qav = (const uint32_t*)&qa;
    const uint32_t* qbv = (const uint32_t*)&qb;
    const uint32_t* kav = (const uint32_t*)&ka;
    const uint32_t* kbv = (const uint32_t*)&kb;
    uint32_t* qov = (uint32_t*)&qo;
    uint32_t* kov = (uint32_t*)&ko;
#pragma unroll
    for (int j = 0; j < 4; j++) {
        __half2 qah = *(const __half2*)&qav[j];
        __half2 qbh = *(const __half2*)&qbv[j];
        __half2 kah = *(const __half2*)&kav[j];
        __half2 kbh = *(const __half2*)&kbv[j];
        float c0 = ct[2 * j], c1 = ct[2 * j + 1];
        float s0 = st[2 * j], s1 = st[2 * j + 1];
        float q0 = __low2float(qah) * c0 + sgn * __low2float(qbh) * s0;
        float q1 = __high2float(qah) * c1 + sgn * __high2float(qbh) * s1;
        float k0 = __low2float(kah) * c0 + sgn * __low2float(kbh) * s0;
        float k1 = __high2float(kah) * c1 + sgn * __high2float(kbh) * s1;
        __half2 qh = __floats2half2_rn(q0, q1);
        __half2 kh = __floats2half2_rn(k0, k1);
        qov[j] = *(uint32_t*)&qh;
        kov[j] = *(uint32_t*)&kh;
    }

    size_t dst = ((size_t)bh * T_ + t) * D_ + dv;
    *(uint4*)&gq_s[dst] = qo;
    *(uint4*)&gk_s[dst] = ko;
    *(uint4*)&gv_s[dst] = va;
}

// ---------------------------------------------------------------------------
// Flash attention (causal) on HMMA, all single fp16.  KV tile = 128 keys.
// CTA = (128 q rows, one bh); 8 warps of 16 rows; 2-stage cp.async.
// ---------------------------------------------------------------------------
#define KV_STG 65536                     // K 32K + V 32K
#define ATTN_SMEM (32768 + 2 * KV_STG)   // Q 32K + 2 KV stages = 160 KB

__device__ __forceinline__ void attn_load_kv(
    uint32_t skv, int stage,
    const __half* __restrict__ ks, const __half* __restrict__ vs,
    int k0, int tid)
{
    uint32_t st = skv + stage * KV_STG;
    const __half* srcs[2] = {ks, vs};
#pragma unroll
    for (int u = 0; u < 16; u++) {
        int idx = u * 256 + tid;
        int a = u >> 3;                     // 0=K, 1=V
        int rem = idx & 2047;
        int r = rem >> 4, c = rem & 15;
        uint32_t dst = st + a * 32768 + r * 256 + ((c ^ (r & 7)) << 4);
        CP_ASYNC16(dst, srcs[a] + (size_t)(k0 + r) * D_ + c * 8);
    }
}

__global__ void __launch_bounds__(256, 1) attn_mma_kernel()
{
    extern __shared__ __align__(1024) char smem[];
    const uint32_t sb = smem_u32(smem);
    const int tid = threadIdx.x;
    const int w = tid >> 5, lane = tid & 31;
    const int g = lane >> 2, tig = lane & 3;
    const int qt = (int)gridDim.x - 1 - (int)blockIdx.x;   // heavy tiles first
    const int bh = blockIdx.y;
    const int q0 = qt * 128;
    const int NT = qt + 1;                                  // 128-key tiles

    const size_t hb = (size_t)bh * T_ * D_;
    const __half* Qs = gq_s + hb;
    const __half* Ks = gk_s + hb;
    const __half* Vs = gv_s + hb;

    const uint32_t sq = sb;
    const uint32_t skv = sb + 32768;

    // Load Q tile; + KV stage 0 — one group
#pragma unroll
    for (int u = 0; u < 8; u++) {
        int idx = u * 256 + tid;
        int r = idx >> 4, c = idx & 15;
        uint32_t dst = sq + r * 256 + ((c ^ (r & 7)) << 4);
        CP_ASYNC16(dst, Qs + (size_t)(q0 + r) * D_ + c * 8);
    }
    attn_load_kv(skv, 0, Ks, Vs, 0, tid);
    CP_COMMIT();

    float O[16][4];
#pragma unroll
    for (int i = 0; i < 16; i++)
#pragma unroll
        for (int j = 0; j < 4; j++) O[i][j] = 0.f;
    float m0 = -1e30f, m1 = -1e30f, l0 = 0.f, l1 = 0.f;
    const float scale = 0.08838834764831845f;
    const int row0 = q0 + w * 16 + g;
    const int row1 = row0 + 8;

    for (int kt = 0; kt < NT; kt++) {
        CP_WAIT_GROUP(0);
        __syncthreads();
        if (kt + 1 < NT)
            attn_load_kv(skv, (kt + 1) & 1, Ks, Vs, (kt + 1) * 128, tid);
        CP_COMMIT();
        const uint32_t sk = skv + (kt & 1) * KV_STG;

        // S = Q K^T  (128 q x 128 k)
        float S[16][4];
#pragma unroll
        for (int i = 0; i < 16; i++)
#pragma unroll
            for (int j = 0; j < 4; j++) S[i][j] = 0.f;

#pragma unroll
        for (int ks = 0; ks < 8; ks++) {
            int qrow = w * 16 + (lane & 15);
            int qc = 2 * ks + (lane >> 4);
            uint32_t qa = sq + qrow * 256 + ((qc ^ (qrow & 7)) << 4);
            uint32_t af[4];
            LDMATRIX_X4(af[0], af[1], af[2], af[3], qa);
#pragma unroll
            for (int np = 0; np < 8; np++) {
                int kr = np * 16 + (lane & 7) + ((lane >> 4) << 3);
                int kc = 2 * ks + ((lane >> 3) & 1);
                uint32_t ka = sk + kr * 256 + ((kc ^ (kr & 7)) << 4);
                uint32_t kf[4];
                LDMATRIX_X4(kf[0], kf[1], kf[2], kf[3], ka);
                MMA_FP16(S[2 * np],     af, kf);
                MMA_FP16(S[2 * np + 1], af, kf + 2);
            }
        }

        // scale + causal mask (diagonal tile only)
        const bool dom = (kt == qt);
#pragma unroll
        for (int nt = 0; nt < 16; nt++)
#pragma unroll
            for (int q = 0; q < 4; q++) {
                float v = S[nt][q] * scale;
                if (dom) {
                    int col = kt * 128 + nt * 8 + 2 * tig + (q & 1);
                    int row = (q < 2) ? row0 : row1;
                    if (col > row) v = -1e30f;
                }
                S[nt][q] = v;
            }

        // online softmax
        float mx0 = -1e30f, mx1 = -1e30f;
#pragma unroll
        for (int nt = 0; nt < 16; nt++) {
            mx0 = fmaxf(mx0, fmaxf(S[nt][0], S[nt][1]));
            mx1 = fmaxf(mx1, fmaxf(S[nt][2], S[nt][3]));
        }
        mx0 = fmaxf(mx0, __shfl_xor_sync(0xffffffffu, mx0, 1));
        mx0 = fmaxf(mx0, __shfl_xor_sync(0xffffffffu, mx0, 2));
        mx1 = fmaxf(mx1, __shfl_xor_sync(0xffffffffu, mx1, 1));
        mx1 = fmaxf(mx1, __shfl_xor_sync(0xffffffffu, mx1, 2));
        float mn0 = fmaxf(m0, mx0), mn1 = fmaxf(m1, mx1);
        float a0 = __expf(m0 - mn0), a1 = __expf(m1 - mn1);
        m0 = mn0; m1 = mn1;
        float s0 = 0.f, s1 = 0.f;
#pragma unroll
        for (int nt = 0; nt < 16; nt++) {
            S[nt][0] = __expf(S[nt][0] - mn0); s0 += S[nt][0];
            S[nt][1] = __expf(S[nt][1] - mn0); s0 += S[nt][1];
            S[nt][2] = __expf(S[nt][2] - mn1); s1 += S[nt][2];
            S[nt][3] = __expf(S[nt][3] - mn1); s1 += S[nt][3];
        }
        s0 += __shfl_xor_sync(0xffffffffu, s0, 1);
        s0 += __shfl_xor_sync(0xffffffffu, s0, 2);
        s1 += __shfl_xor_sync(0xffffffffu, s1, 1);
        s1 += __shfl_xor_sync(0xffffffffu, s1, 2);
        l0 = l0 * a0 + s0;
        l1 = l1 * a1 + s1;
#pragma unroll
        for (int nt = 0; nt < 16; nt++) {
            O[nt][0] *= a0; O[nt][1] *= a0;
            O[nt][2] *= a1; O[nt][3] *= a1;
        }

        // O += P V  (P fp16, V fp16; key dim 128)
#pragma unroll
        for (int j = 0; j < 8; j++) {
            uint32_t pa[4];
            {
                __half2 h;
                h = __floats2half2_rn(S[2 * j][0],     S[2 * j][1]);     pa[0] = *(uint32_t*)&h;
                h = __floats2half2_rn(S[2 * j][2],     S[2 * j][3]);     pa[1] = *(uint32_t*)&h;
                h = __floats2half2_rn(S[2 * j + 1][0], S[2 * j + 1][1]); pa[2] = *(uint32_t*)&h;
                h = __floats2half2_rn(S[2 * j + 1][2], S[2 * j + 1][3]); pa[3] = *(uint32_t*)&h;
            }
#pragma unroll
            for (int np = 0; np < 8; np++) {
                int vr = j * 16 + (lane & 15);
                int vc = 2 * np + (lane >> 4);
                uint32_t va = sk + 32768 + vr * 256 + ((vc ^ (vr & 7)) << 4);
                uint32_t vf[4];
                LDMATRIX_X4_T(vf[0], vf[1], vf[2], vf[3], va);
                MMA_FP16(O[2 * np],     pa, vf);
                MMA_FP16(O[2 * np + 1], pa, vf + 2);
            }
        }
    }

    // Epilogue: normalize, stage to smem, write ctx single fp16
    __syncthreads();                          // all warps done with KV smem
    float li0 = 1.0f / l0, li1 = 1.0f / l1;
    float* stg = (float*)smem;
    {
        int r0l = w * 16 + g, r1l = r0l + 8;
#pragma unroll
        for (int nt = 0; nt < 16; nt++) {
            float2 v0 = make_float2(O[nt][0] * li0, O[nt][1] * li0);
            float2 v1 = make_float2(O[nt][2] * li1, O[nt][3] * li1);
            *(float2*)&stg[r0l * 132 + nt * 8 + 2 * tig] = v0;
            *(float2*)&stg[r1l * 132 + nt * 8 + 2 * tig] = v1;
        }
    }
    __syncthreads();
    {
        int r = tid >> 1, ch = (tid & 1) * 64;
        int b = bh >> 4, h = bh & 15;
        size_t base = ((size_t)(b * T_ + q0 + r)) * C_ + h * 128 + ch;
#pragma unroll
        for (int c = 0; c < 64; c += 2) {
            float x = stg[r * 132 + ch + c], y = stg[r * 132 + ch + c + 1];
            *(__half2*)&gcx_s[base + c] = __floats2half2_rn(x, y);
        }
    }
}

// ---------------------------------------------------------------------------
extern "C" void kernel_launch(void* const* d_in, const int* in_sizes, int n_in,
                              void* d_out, int out_size)
{
    const float* x = nullptr; const float* w_qkv = nullptr;
    const float* w_proj = nullptr; const float* b_proj = nullptr;
    for (int i = 0; i < n_in; i++) {
        switch (in_sizes[i]) {
            case M_ * C_:  x      = (const float*)d_in[i]; break;
            case C_ * N3_: w_qkv  = (const float*)d_in[i]; break;
            case C_ * C_:  w_proj = (const float*)d_in[i]; break;
            case C_:       b_proj = (const float*)d_in[i]; break;
        }
    }
    float* out = (float*)d_out;

    void *p_qkv16, *p_x, *p_cx, *p_wq, *p_wp;
    cudaGetSymbolAddress(&p_qkv16, g_qkv16);
    cudaGetSymbolAddress(&p_x,   gx_s);
    cudaGetSymbolAddress(&p_cx,  gcx_s);
    cudaGetSymbolAddress(&p_wq,  gwq);
    cudaGetSymbolAddress(&p_wp,  gwp);

    cudaFuncSetAttribute(gemm_mma_kernel<0>,
                         cudaFuncAttributeMaxDynamicSharedMemorySize, GEMM_SMEM);
    cudaFuncSetAttribute(gemm_mma_kernel<1>,
                         cudaFuncAttributeMaxDynamicSharedMemorySize, GEMM_SMEM);
    cudaFuncSetAttribute(attn_mma_kernel,
                         cudaFuncAttributeMaxDynamicSharedMemorySize, ATTN_SMEM);

    // 1) operand prep
    rope_table_kernel<<<(T_ * 64 + 255) / 256, 256>>>();
    round_kernel<<<(M_ * C_ / 4 + 255) / 256, 256>>>(
        x, (__half*)p_x, M_ * C_ / 4);
    transpose_h_kernel<<<dim3(N3_ / 32, C_ / 32), dim3(32, 8)>>>(
        w_qkv, (__half*)p_wq, C_, N3_);
    transpose_h_kernel<<<dim3(C_ / 32, C_ / 32), dim3(32, 8)>>>(
        w_proj, (__half*)p_wp, C_, C_);

    // 2) QKV GEMM (persistent HMMA fp16) -> fp16 output
    gemm_mma_kernel<1><<<GEMM_GRID, 256, GEMM_SMEM>>>(
        (const __half*)p_x, (const __half*)p_wq,
        nullptr, (__half*)p_qkv16, nullptr, N3_, C_,
        N3_ / 128, (N3_ / 128) * (M_ / 128));

    // 3) RoPE (vectorized) -> single fp16 q/k/v
    rope_kernel<<<(BH_ * T_ * 16) / 256, 256>>>();

    // 4) causal flash attention on HMMA (KV tile 128)
    attn_mma_kernel<<<dim3(T_ / 128, BH_), 256, ATTN_SMEM>>>();

    // 5) projection GEMM (persistent HMMA fp16) + bias -> fp32 out
    gemm_mma_kernel<0><<<GEMM_GRID, 256, GEMM_SMEM>>>(
        (const __half*)p_cx, (const __half*)p_wp,
        out, nullptr, b_proj, C_, C_,
        C_ / 128, (C_ / 128) * (M_ / 128));
}

// round 13
// speedup vs baseline: 1.1234x; 1.1234x over previous
#include <cuda_runtime.h>
#include <cuda_bf16.h>
#include <cuda_fp16.h>
#include <math.h>
#include <stdint.h>

// Problem constants
#define B_   4
#define T_   2048
#define C_   2048
#define H_   16
#define D_   128
#define BH_  (B_ * H_)        // 64
#define M_   (B_ * T_)        // 8192
#define N3_  (3 * C_)         // 6144

// ============================ helpers ======================================
__device__ __forceinline__ uint32_t smem_u32(const void* p) {
    uint32_t a;
    asm("{ .reg .u64 t; cvta.to.shared.u64 t, %1; cvt.u32.u64 %0, t; }"
        : "=r"(a) : "l"(p));
    return a;
}
#define CP_ASYNC16(saddr, gptr) \
    asm volatile("cp.async.cg.shared.global [%0], [%1], 16;" \
                 :: "r"(saddr), "l"(gptr) : "memory")
#define CP_COMMIT() asm volatile("cp.async.commit_group;" ::: "memory")
#define CP_WAIT_GROUP(n) asm volatile("cp.async.wait_group %0;" :: "n"(n) : "memory")

#define LDMATRIX_X4(r0, r1, r2, r3, addr) \
    asm volatile("ldmatrix.sync.aligned.m8n8.x4.shared.b16 {%0,%1,%2,%3}, [%4];" \
                 : "=r"(r0), "=r"(r1), "=r"(r2), "=r"(r3) : "r"(addr))
#define LDMATRIX_X4_T(r0, r1, r2, r3, addr) \
    asm volatile("ldmatrix.sync.aligned.m8n8.x4.trans.shared.b16 {%0,%1,%2,%3}, [%4];" \
                 : "=r"(r0), "=r"(r1), "=r"(r2), "=r"(r3) : "r"(addr))
#define MMA_FP16(c, a, b) \
    asm volatile("mma.sync.aligned.m16n8k16.row.col.f32.f16.f16.f32 " \
                 "{%0,%1,%2,%3}, {%4,%5,%6,%7}, {%8,%9}, {%0,%1,%2,%3};" \
                 : "+f"((c)[0]), "+f"((c)[1]), "+f"((c)[2]), "+f"((c)[3]) \
                 : "r"((a)[0]), "r"((a)[1]), "r"((a)[2]), "r"((a)[3]), \
                   "r"((b)[0]), "r"((b)[1]))

// ---------------- scratch (device globals; no allocation allowed) ----------
__device__ __half g_qkv16[M_ * N3_];       // [8192, 6144] fp16 (QKV pre-rope)
__device__ float g_cos[T_ * 64];
__device__ float g_sin[T_ * 64];
__device__ __half gx_s[M_ * C_];           // activations [M,K]
__device__ __half gcx_s[M_ * C_];          // ctx [M,K]
__device__ __half gwq[N3_ * C_];           // W_qkv^T [N,K]
__device__ __half gwp[C_ * C_];            // W_proj^T [N,K]
__device__ __half gq_s[BH_ * T_ * D_];
__device__ __half gk_s[BH_ * T_ * D_];
__device__ __half gv_s[BH_ * T_ * D_];

// ---------------------------------------------------------------------------
// round fp32 -> fp16, elementwise (vectorized by 4)
// ---------------------------------------------------------------------------
__global__ void __launch_bounds__(256) round_kernel(
    const float* __restrict__ in, __half* __restrict__ out16, int n4)
{
    int i = blockIdx.x * 256 + threadIdx.x;
    if (i >= n4) return;
    float4 v = ((const float4*)in)[i];
    __half2* hp = (__half2*)out16;
    hp[i * 2 + 0] = __floats2half2_rn(v.x, v.y);
    hp[i * 2 + 1] = __floats2half2_rn(v.z, v.w);
}

// ---------------------------------------------------------------------------
// transpose + round: W[K,N] fp32 -> Wh[N,K] fp16
// ---------------------------------------------------------------------------
__global__ void __launch_bounds__(256) transpose_h_kernel(
    const float* __restrict__ W, __half* __restrict__ Th, int K, int N)
{
    __shared__ float t[32][33];
    int bn = blockIdx.x * 32;
    int bk = blockIdx.y * 32;
    int x = threadIdx.x, y = threadIdx.y;       // 32 x 8
#pragma unroll
    for (int i = 0; i < 32; i += 8)
        t[y + i][x] = W[(size_t)(bk + y + i) * N + bn + x];
    __syncthreads();
#pragma unroll
    for (int i = 0; i < 32; i += 8) {
        float v = t[x][y + i];                  // = W[bk+x][bn+y+i]
        Th[(size_t)(bn + y + i) * K + bk + x] = __float2half_rn(v);
    }
}

// ---------------------------------------------------------------------------
// HMMA GEMM: C[M,N] = A[M,K] @ B[N,K]^T, plain fp16 x fp16, fp32 accum.
// CTA 128x128, BK=64, 3-stage cp.async (wait_group 1), 8 warps, 2 CTAs/SM.
// OUT16=0: fp32 epilogue (+bias). OUT16=1: fp16 epilogue (no bias).
// NOTE: unconditional CP_COMMIT per iteration is load-bearing for the
// wait_group(1) accounting. Kernel is at the 128-reg limit — do not add state.
// ---------------------------------------------------------------------------
#define STG_BYTES 32768              // A 16K + B 16K
#define OFF_A 0
#define OFF_B 16384
#define GEMM_SMEM (3 * STG_BYTES)    // 96 KB

__device__ __forceinline__ void gemm_load_stage(
    uint32_t sb, int stage,
    const __half* __restrict__ A, const __half* __restrict__ Bh,
    int row0, int col0, int kb, int K, int tid)
{
    uint32_t st = sb + stage * STG_BYTES;
    const int k0 = kb * 64;
#pragma unroll
    for (int u = 0; u < 4; u++) {
        int idx = u * 256 + tid;                 // 1024 16B chunks per operand
        int r = idx >> 3, c = idx & 7;
        uint32_t sw = (uint32_t)(r * 128 + ((c ^ (r & 7)) << 4));
        size_t ga = (size_t)(row0 + r) * K + k0 + c * 8;
        size_t gb = (size_t)(col0 + r) * K + k0 + c * 8;
        CP_ASYNC16(st + OFF_A + sw, A + ga);
        CP_ASYNC16(st + OFF_B + sw, Bh + gb);
    }
}

template<int OUT16>
__global__ void __launch_bounds__(256, 2) gemm_mma_kernel(
    const __half* __restrict__ A, const __half* __restrict__ Bh,
    float* __restrict__ Cout, __half* __restrict__ Cout16,
    const float* __restrict__ bias, int N, int K)
{
    extern __shared__ __align__(1024) char smem[];
    const uint32_t sb = smem_u32(smem);
    const int tid = threadIdx.x;
    const int wid = tid >> 5, lane = tid & 31;
    const int wr = wid >> 2, wc = wid & 3;       // warp grid 2 x 4
    const int col0 = blockIdx.x * 128;
    const int row0 = blockIdx.y * 128;
    const int NK = K / 64;

    float acc[4][4][4];
#pragma unroll
    for (int i = 0; i < 4; i++)
#pragma unroll
        for (int j = 0; j < 4; j++)
#pragma unroll
            for (int k = 0; k < 4; k++) acc[i][j][k] = 0.f;

    gemm_load_stage(sb, 0, A, Bh, row0, col0, 0, K, tid);
    CP_COMMIT();
    gemm_load_stage(sb, 1, A, Bh, row0, col0, 1, K, tid);
    CP_COMMIT();

    const int a_row = wr * 64 + (lane & 15);
    const int a_cg  = (lane >> 4);
    const int b_row = wc * 32 + (lane & 7) + ((lane >> 4) << 3);
    const int b_cg  = ((lane >> 3) & 1);

    int slot = 0, nslot = 2;
    for (int kb = 0; kb < NK; kb++) {
        CP_WAIT_GROUP(1);
        __syncthreads();
        if (kb + 2 < NK)
            gemm_load_stage(sb, nslot, A, Bh, row0, col0, kb + 2, K, tid);
        CP_COMMIT();

        uint32_t st = sb + slot * STG_BYTES;
#pragma unroll
        for (int ks = 0; ks < 4; ks++) {
            uint32_t af[4][4], bf[4][2];
#pragma unroll
            for (int mt = 0; mt < 4; mt++) {
                int r = a_row + mt * 16;
                int c = ks * 2 + a_cg;
                uint32_t ad = st + (uint32_t)(r * 128 + ((c ^ (r & 7)) << 4));
                LDMATRIX_X4(af[mt][0], af[mt][1], af[mt][2], af[mt][3], ad + OFF_A);
            }
#pragma unroll
            for (int ntp = 0; ntp < 2; ntp++) {
                int n = b_row + ntp * 16;
                int c = ks * 2 + b_cg;
                uint32_t bd = st + (uint32_t)(n * 128 + ((c ^ (n & 7)) << 4));
                LDMATRIX_X4(bf[2 * ntp][0], bf[2 * ntp][1],
                            bf[2 * ntp + 1][0], bf[2 * ntp + 1][1], bd + OFF_B);
            }
#pragma unroll
            for (int mt = 0; mt < 4; mt++)
#pragma unroll
                for (int nt = 0; nt < 4; nt++)
                    MMA_FP16(acc[mt][nt], af[mt], bf[nt]);
        }
        slot = (slot == 2) ? 0 : slot + 1;
        nslot = (nslot == 2) ? 0 : nslot + 1;
    }

    const int er = lane >> 2;
    const int ec = (lane & 3) * 2;
#pragma unroll
    for (int mt = 0; mt < 4; mt++) {
        int row = row0 + wr * 64 + mt * 16 + er;
#pragma unroll
        for (int nt = 0; nt < 4; nt++) {
            int col = col0 + wc * 32 + nt * 8 + ec;
            if (OUT16) {
                *(__half2*)&Cout16[(size_t)row * N + col] =
                    __floats2half2_rn(acc[mt][nt][0], acc[mt][nt][1]);
                *(__half2*)&Cout16[(size_t)(row + 8) * N + col] =
                    __floats2half2_rn(acc[mt][nt][2], acc[mt][nt][3]);
            } else {
                float b0 = 0.f, b1 = 0.f;
                if (bias) { b0 = bias[col]; b1 = bias[col + 1]; }
                float2 v0, v1;
                v0.x = acc[mt][nt][0] + b0; v0.y = acc[mt][nt][1] + b1;
                v1.x = acc[mt][nt][2] + b0; v1.y = acc[mt][nt][3] + b1;
                *(float2*)&Cout[(size_t)row * N + col] = v0;
                *(float2*)&Cout[(size_t)(row + 8) * N + col] = v1;
            }
        }
    }
}

// ---------------------------------------------------------------------------
// RoPE table
// ---------------------------------------------------------------------------
__global__ void rope_table_kernel()
{
    int g = blockIdx.x * blockDim.x + threadIdx.x;
    if (g >= T_ * 64) return;
    int t = g >> 6, i = g & 63;
    double invf = pow(10000.0, -(double)i / 64.0);
    float  angf = (float)t * (float)invf;
    double ang  = (double)angf;
    g_cos[g] = (float)cos(ang);
    g_sin[g] = (float)sin(ang);
}

// ---------------------------------------------------------------------------
// RoPE (vectorized 8 halves/thread): g_qkv16[B,T,3C] -> q/k/v fp16 [BH,T,D]
// ---------------------------------------------------------------------------
__global__ void __launch_bounds__(256) rope_kernel()
{
    int g = blockIdx.x * 256 + threadIdx.x;     // BH*T*16 threads
    int dv = (g & 15) * 8;                      // 0,8,...,120
    int t  = (g >> 4) & 2047;
    int bh = g >> 15;
    int b  = bh >> 4, h = bh & 15;

    size_t src  = ((size_t)(b * T_ + t)) * N3_ + h * D_ + dv;
    size_t srcp = src - dv + (dv ^ 64);

    uint4 qa = *(const uint4*)&g_qkv16[src];
    uint4 qb = *(const uint4*)&g_qkv16[srcp];
    uint4 ka = *(const uint4*)&g_qkv16[src + C_];
    uint4 kb = *(const uint4*)&g_qkv16[srcp + C_];
    uint4 va = *(const uint4*)&g_qkv16[src + 2 * C_];

    float sgn = (dv < 64) ? -1.f : 1.f;
    int i0 = dv & 63;
    const float* ct = g_cos + t * 64 + i0;
    const float* st = g_sin + t * 64 + i0;

    uint4 qo, ko;
    const uint32_t* qav = (const uint32_t*)&qa;
    const uint32_t* qbv = (const uint32_t*)&qb;
    const uint32_t* kav = (const uint32_t*)&ka;
    const uint32_t* kbv = (const uint32_t*)&kb;
    uint32_t* qov = (uint32_t*)&qo;
    uint32_t* kov = (uint32_t*)&ko;
#pragma unroll
    for (int j = 0; j < 4; j++) {
        __half2 qah = *(const __half2*)&qav[j];
        __half2 qbh = *(const __half2*)&qbv[j];
        __half2 kah = *(const __half2*)&kav[j];
        __half2 kbh = *(const __half2*)&kbv[j];
        float c0 = ct[2 * j], c1 = ct[2 * j + 1];
        float s0 = st[2 * j], s1 = st[2 * j + 1];
        float q0 = __low2float(qah) * c0 + sgn * __low2float(qbh) * s0;
        float q1 = __high2float(qah) * c1 + sgn * __high2float(qbh) * s1;
        float k0 = __low2float(kah) * c0 + sgn * __low2float(kbh) * s0;
        float k1 = __high2float(kah) * c1 + sgn * __high2float(kbh) * s1;
        __half2 qh = __floats2half2_rn(q0, q1);
        __half2 kh = __floats2half2_rn(k0, k1);
        qov[j] = *(uint32_t*)&qh;
        kov[j] = *(uint32_t*)&kh;
    }

    size_t dst = ((size_t)bh * T_ + t) * D_ + dv;
    *(uint4*)&gq_s[dst] = qo;
    *(uint4*)&gk_s[dst] = ko;
    *(uint4*)&gv_s[dst] = va;
}

// ---------------------------------------------------------------------------
// Flash attention (causal) on HMMA, all single fp16.  KV tile = 128 keys.
// CTA = (128 q rows, one bh); 8 warps of 16 rows; 2-stage cp.async.
// Softmax in base-2 domain (scale pre-multiplied by log2(e); exp2f = MUFU only).
// ---------------------------------------------------------------------------
#define KV_STG 65536                     // K 32K + V 32K
#define ATTN_SMEM (32768 + 2 * KV_STG)   // Q 32K + 2 KV stages = 160 KB

__device__ __forceinline__ void attn_load_kv(
    uint32_t skv, int stage,
    const __half* __restrict__ ks, const __half* __restrict__ vs,
    int k0, int tid)
{
    uint32_t st = skv + stage * KV_STG;
    const __half* srcs[2] = {ks, vs};
#pragma unroll
    for (int u = 0; u < 16; u++) {
        int idx = u * 256 + tid;
        int a = u >> 3;                     // 0=K, 1=V
        int rem = idx & 2047;
        int r = rem >> 4, c = rem & 15;
        uint32_t dst = st + a * 32768 + r * 256 + ((c ^ (r & 7)) << 4);
        CP_ASYNC16(dst, srcs[a] + (size_t)(k0 + r) * D_ + c * 8);
    }
}

__global__ void __launch_bounds__(256, 1) attn_mma_kernel()
{
    extern __shared__ __align__(1024) char smem[];
    const uint32_t sb = smem_u32(smem);
    const int tid = threadIdx.x;
    const int w = tid >> 5, lane = tid & 31;
    const int g = lane >> 2, tig = lane & 3;
    const int qt = (int)gridDim.x - 1 - (int)blockIdx.x;   // heavy tiles first
    const int bh = blockIdx.y;
    const int q0 = qt * 128;
    const int NT = qt + 1;                                  // 128-key tiles

    const size_t hb = (size_t)bh * T_ * D_;
    const __half* Qs = gq_s + hb;
    const __half* Ks = gk_s + hb;
    const __half* Vs = gv_s + hb;

    const uint32_t sq = sb;
    const uint32_t skv = sb + 32768;

    // Load Q tile; + KV stage 0 — one group
#pragma unroll
    for (int u = 0; u < 8; u++) {
        int idx = u * 256 + tid;
        int r = idx >> 4, c = idx & 15;
        uint32_t dst = sq + r * 256 + ((c ^ (r & 7)) << 4);
        CP_ASYNC16(dst, Qs + (size_t)(q0 + r) * D_ + c * 8);
    }
    attn_load_kv(skv, 0, Ks, Vs, 0, tid);
    CP_COMMIT();

    float O[16][4];
#pragma unroll
    for (int i = 0; i < 16; i++)
#pragma unroll
        for (int j = 0; j < 4; j++) O[i][j] = 0.f;
    float m0 = -1e30f, m1 = -1e30f, l0 = 0.f, l1 = 0.f;
    const float scale2 = 0.08838834764831845f * 1.4426950408889634f;  // /sqrt(D) * log2(e)
    const int row0 = q0 + w * 16 + g;
    const int row1 = row0 + 8;

    for (int kt = 0; kt < NT; kt++) {
        CP_WAIT_GROUP(0);
        __syncthreads();
        if (kt + 1 < NT)
            attn_load_kv(skv, (kt + 1) & 1, Ks, Vs, (kt + 1) * 128, tid);
        CP_COMMIT();
        const uint32_t sk = skv + (kt & 1) * KV_STG;

        // S = Q K^T  (128 q x 128 k)
        float S[16][4];
#pragma unroll
        for (int i = 0; i < 16; i++)
#pragma unroll
            for (int j = 0; j < 4; j++) S[i][j] = 0.f;

#pragma unroll
        for (int ks = 0; ks < 8; ks++) {
            int qrow = w * 16 + (lane & 15);
            int qc = 2 * ks + (lane >> 4);
            uint32_t qa = sq + qrow * 256 + ((qc ^ (qrow & 7)) << 4);
            uint32_t af[4];
            LDMATRIX_X4(af[0], af[1], af[2], af[3], qa);
#pragma unroll
            for (int np = 0; np < 8; np++) {
                int kr = np * 16 + (lane & 7) + ((lane >> 4) << 3);
                int kc = 2 * ks + ((lane >> 3) & 1);
                uint32_t ka = sk + kr * 256 + ((kc ^ (kr & 7)) << 4);
                uint32_t kf[4];
                LDMATRIX_X4(kf[0], kf[1], kf[2], kf[3], ka);
                MMA_FP16(S[2 * np],     af, kf);
                MMA_FP16(S[2 * np + 1], af, kf + 2);
            }
        }

        // scale (base-2 domain) + causal mask (diagonal tile only)
        const bool dom = (kt == qt);
#pragma unroll
        for (int nt = 0; nt < 16; nt++)
#pragma unroll
            for (int q = 0; q < 4; q++) {
                float v = S[nt][q] * scale2;
                if (dom) {
                    int col = kt * 128 + nt * 8 + 2 * tig + (q & 1);
                    int row = (q < 2) ? row0 : row1;
                    if (col > row) v = -1e30f;
                }
                S[nt][q] = v;
            }

        // online softmax (base-2)
        float mx0 = -1e30f, mx1 = -1e30f;
#pragma unroll
        for (int nt = 0; nt < 16; nt++) {
            mx0 = fmaxf(mx0, fmaxf(S[nt][0], S[nt][1]));
            mx1 = fmaxf(mx1, fmaxf(S[nt][2], S[nt][3]));
        }
        mx0 = fmaxf(mx0, __shfl_xor_sync(0xffffffffu, mx0, 1));
        mx0 = fmaxf(mx0, __shfl_xor_sync(0xffffffffu, mx0, 2));
        mx1 = fmaxf(mx1, __shfl_xor_sync(0xffffffffu, mx1, 1));
        mx1 = fmaxf(mx1, __shfl_xor_sync(0xffffffffu, mx1, 2));
        float mn0 = fmaxf(m0, mx0), mn1 = fmaxf(m1, mx1);
        float a0 = exp2f(m0 - mn0), a1 = exp2f(m1 - mn1);
        m0 = mn0; m1 = mn1;
        float s0 = 0.f, s1 = 0.f;
#pragma unroll
        for (int nt = 0; nt < 16; nt++) {
            S[nt][0] = exp2f(S[nt][0] - mn0); s0 += S[nt][0];
            S[nt][1] = exp2f(S[nt][1] - mn0); s0 += S[nt][1];
            S[nt][2] = exp2f(S[nt][2] - mn1); s1 += S[nt][2];
            S[nt][3] = exp2f(S[nt][3] - mn1); s1 += S[nt][3];
        }
        s0 += __shfl_xor_sync(0xffffffffu, s0, 1);
        s0 += __shfl_xor_sync(0xffffffffu, s0, 2);
        s1 += __shfl_xor_sync(0xffffffffu, s1, 1);
        s1 += __shfl_xor_sync(0xffffffffu, s1, 2);
        l0 = l0 * a0 + s0;
        l1 = l1 * a1 + s1;
#pragma unroll
        for (int nt = 0; nt < 16; nt++) {
            O[nt][0] *= a0; O[nt][1] *= a0;
            O[nt][2] *= a1; O[nt][3] *= a1;
        }

        // O += P V  (P fp16, V fp16; key dim 128)
#pragma unroll
        for (int j = 0; j < 8; j++) {
            uint32_t pa[4];
            {
                __half2 h;
                h = __floats2half2_rn(S[2 * j][0],     S[2 * j][1]);     pa[0] = *(uint32_t*)&h;
                h = __floats2half2_rn(S[2 * j][2],     S[2 * j][3]);     pa[1] = *(uint32_t*)&h;
                h = __floats2half2_rn(S[2 * j + 1][0], S[2 * j + 1][1]); pa[2] = *(uint32_t*)&h;
                h = __floats2half2_rn(S[2 * j + 1][2], S[2 * j + 1][3]); pa[3] = *(uint32_t*)&h;
            }
#pragma unroll
            for (int np = 0; np < 8; np++) {
                int vr = j * 16 + (lane & 15);
                int vc = 2 * np + (lane >> 4);
                uint32_t va = sk + 32768 + vr * 256 + ((vc ^ (vr & 7)) << 4);
                uint32_t vf[4];
                LDMATRIX_X4_T(vf[0], vf[1], vf[2], vf[3], va);
                MMA_FP16(O[2 * np],     pa, vf);
                MMA_FP16(O[2 * np + 1], pa, vf + 2);
            }
        }
    }

    // Epilogue: normalize, stage to smem, write ctx single fp16
    __syncthreads();                          // all warps done with KV smem
    float li0 = 1.0f / l0, li1 = 1.0f / l1;
    float* stg = (float*)smem;
    {
        int r0l = w * 16 + g, r1l = r0l + 8;
#pragma unroll
        for (int nt = 0; nt < 16; nt++) {
            float2 v0 = make_float2(O[nt][0] * li0, O[nt][1] * li0);
            float2 v1 = make_float2(O[nt][2] * li1, O[nt][3] * li1);
            *(float2*)&stg[r0l * 132 + nt * 8 + 2 * tig] = v0;
            *(float2*)&stg[r1l * 132 + nt * 8 + 2 * tig] = v1;
        }
    }
    __syncthreads();
    {
        int r = tid >> 1, ch = (tid & 1) * 64;
        int b = bh >> 4, h = bh & 15;
        size_t base = ((size_t)(b * T_ + q0 + r)) * C_ + h * 128 + ch;
#pragma unroll
        for (int c = 0; c < 64; c += 2) {
            float x = stg[r * 132 + ch + c], y = stg[r * 132 + ch + c + 1];
            *(__half2*)&gcx_s[base + c] = __floats2half2_rn(x, y);
        }
    }
}

// ---------------------------------------------------------------------------
extern "C" void kernel_launch(void* const* d_in, const int* in_sizes, int n_in,
                              void* d_out, int out_size)
{
    const float* x = nullptr; const float* w_qkv = nullptr;
    const float* w_proj = nullptr; const float* b_proj = nullptr;
    for (int i = 0; i < n_in; i++) {
        switch (in_sizes[i]) {
            case M_ * C_:  x      = (const float*)d_in[i]; break;
            case C_ * N3_: w_qkv  = (const float*)d_in[i]; break;
            case C_ * C_:  w_proj = (const float*)d_in[i]; break;
            case C_:       b_proj = (const float*)d_in[i]; break;
        }
    }
    float* out = (float*)d_out;

    void *p_qkv16, *p_x, *p_cx, *p_wq, *p_wp;
    cudaGetSymbolAddress(&p_qkv16, g_qkv16);
    cudaGetSymbolAddress(&p_x,   gx_s);
    cudaGetSymbolAddress(&p_cx,  gcx_s);
    cudaGetSymbolAddress(&p_wq,  gwq);
    cudaGetSymbolAddress(&p_wp,  gwp);

    cudaFuncSetAttribute(gemm_mma_kernel<0>,
                         cudaFuncAttributeMaxDynamicSharedMemorySize, GEMM_SMEM);
    cudaFuncSetAttribute(gemm_mma_kernel<1>,
                         cudaFuncAttributeMaxDynamicSharedMemorySize, GEMM_SMEM);
    cudaFuncSetAttribute(attn_mma_kernel,
                         cudaFuncAttributeMaxDynamicSharedMemorySize, ATTN_SMEM);

    // 1) operand prep
    rope_table_kernel<<<(T_ * 64 + 255) / 256, 256>>>();
    round_kernel<<<(M_ * C_ / 4 + 255) / 256, 256>>>(
        x, (__half*)p_x, M_ * C_ / 4);
    transpose_h_kernel<<<dim3(N3_ / 32, C_ / 32), dim3(32, 8)>>>(
        w_qkv, (__half*)p_wq, C_, N3_);
    transpose_h_kernel<<<dim3(C_ / 32, C_ / 32), dim3(32, 8)>>>(
        w_proj, (__half*)p_wp, C_, C_);

    // 2) QKV GEMM (HMMA fp16) -> fp16 output
    gemm_mma_kernel<1><<<dim3(N3_ / 128, M_ / 128), 256, GEMM_SMEM>>>(
        (const __half*)p_x, (const __half*)p_wq,
        nullptr, (__half*)p_qkv16, nullptr, N3_, C_);

    // 3) RoPE (vectorized) -> single fp16 q/k/v
    rope_kernel<<<(BH_ * T_ * 16) / 256, 256>>>();

    // 4) causal flash attention on HMMA (KV tile 128)
    attn_mma_kernel<<<dim3(T_ / 128, BH_), 256, ATTN_SMEM>>>();

    // 5) projection GEMM (HMMA fp16) + bias -> fp32 out
    gemm_mma_kernel<0><<<dim3(C_ / 128, M_ / 128), 256, GEMM_SMEM>>>(
        (const __half*)p_cx, (const __half*)p_wp,
        out, nullptr, b_proj, C_, C_);
}

// round 14
// speedup vs baseline: 1.1503x; 1.0239x over previous
#include <cuda_runtime.h>
#include <cuda_bf16.h>
#include <cuda_fp16.h>
#include <math.h>
#include <stdint.h>

// Problem constants
#define B_   4
#define T_   2048
#define C_   2048
#define H_   16
#define D_   128
#define BH_  (B_ * H_)        // 64
#define M_   (B_ * T_)        // 8192
#define N3_  (3 * C_)         // 6144

// ============================ helpers ======================================
__device__ __forceinline__ uint32_t smem_u32(const void* p) {
    uint32_t a;
    asm("{ .reg .u64 t; cvta.to.shared.u64 t, %1; cvt.u32.u64 %0, t; }"
        : "=r"(a) : "l"(p));
    return a;
}
#define CP_ASYNC16(saddr, gptr) \
    asm volatile("cp.async.cg.shared.global [%0], [%1], 16;" \
                 :: "r"(saddr), "l"(gptr) : "memory")
#define CP_COMMIT() asm volatile("cp.async.commit_group;" ::: "memory")
#define CP_WAIT_GROUP(n) asm volatile("cp.async.wait_group %0;" :: "n"(n) : "memory")

#define LDMATRIX_X4(r0, r1, r2, r3, addr) \
    asm volatile("ldmatrix.sync.aligned.m8n8.x4.shared.b16 {%0,%1,%2,%3}, [%4];" \
                 : "=r"(r0), "=r"(r1), "=r"(r2), "=r"(r3) : "r"(addr))
#define LDMATRIX_X4_T(r0, r1, r2, r3, addr) \
    asm volatile("ldmatrix.sync.aligned.m8n8.x4.trans.shared.b16 {%0,%1,%2,%3}, [%4];" \
                 : "=r"(r0), "=r"(r1), "=r"(r2), "=r"(r3) : "r"(addr))
#define MMA_FP16(c, a, b) \
    asm volatile("mma.sync.aligned.m16n8k16.row.col.f32.f16.f16.f32 " \
                 "{%0,%1,%2,%3}, {%4,%5,%6,%7}, {%8,%9}, {%0,%1,%2,%3};" \
                 : "+f"((c)[0]), "+f"((c)[1]), "+f"((c)[2]), "+f"((c)[3]) \
                 : "r"((a)[0]), "r"((a)[1]), "r"((a)[2]), "r"((a)[3]), \
                   "r"((b)[0]), "r"((b)[1]))

// ---------------- scratch (device globals; no allocation allowed) ----------
__device__ __half g_qkv16[M_ * N3_];       // [8192, 6144] fp16 (QKV pre-rope)
__device__ float g_cos[T_ * 64];
__device__ float g_sin[T_ * 64];
__device__ __half gx_s[M_ * C_];           // activations [M,K]
__device__ __half gcx_s[M_ * C_];          // ctx [M,K]
__device__ __half gwq[N3_ * C_];           // W_qkv^T [N,K]
__device__ __half gwp[C_ * C_];            // W_proj^T [N,K]
__device__ __half gq_s[BH_ * T_ * D_];
__device__ __half gk_s[BH_ * T_ * D_];
__device__ __half gv_s[BH_ * T_ * D_];

// ---------------------------------------------------------------------------
// round fp32 -> fp16, elementwise (vectorized by 4)
// ---------------------------------------------------------------------------
__global__ void __launch_bounds__(256) round_kernel(
    const float* __restrict__ in, __half* __restrict__ out16, int n4)
{
    int i = blockIdx.x * 256 + threadIdx.x;
    if (i >= n4) return;
    float4 v = ((const float4*)in)[i];
    __half2* hp = (__half2*)out16;
    hp[i * 2 + 0] = __floats2half2_rn(v.x, v.y);
    hp[i * 2 + 1] = __floats2half2_rn(v.z, v.w);
}

// ---------------------------------------------------------------------------
// transpose + round: W[K,N] fp32 -> Wh[N,K] fp16
// ---------------------------------------------------------------------------
__global__ void __launch_bounds__(256) transpose_h_kernel(
    const float* __restrict__ W, __half* __restrict__ Th, int K, int N)
{
    __shared__ float t[32][33];
    int bn = blockIdx.x * 32;
    int bk = blockIdx.y * 32;
    int x = threadIdx.x, y = threadIdx.y;       // 32 x 8
#pragma unroll
    for (int i = 0; i < 32; i += 8)
        t[y + i][x] = W[(size_t)(bk + y + i) * N + bn + x];
    __syncthreads();
#pragma unroll
    for (int i = 0; i < 32; i += 8) {
        float v = t[x][y + i];                  // = W[bk+x][bn+y+i]
        Th[(size_t)(bn + y + i) * K + bk + x] = __float2half_rn(v);
    }
}

// ---------------------------------------------------------------------------
// HMMA GEMM: C[M,N] = A[M,K] @ B[N,K]^T, plain fp16 x fp16, fp32 accum.
// CTA 128x128, BK=64, 3-stage cp.async (wait_group 1), 8 warps, 2 CTAs/SM.
// OUT16=0: fp32 epilogue (+bias). OUT16=1: fp16 epilogue (no bias).
// NOTE: unconditional CP_COMMIT per iteration is load-bearing for the
// wait_group(1) accounting. Kernel is at the 128-reg limit — do not add state.
// ---------------------------------------------------------------------------
#define STG_BYTES 32768              // A 16K + B 16K
#define OFF_A 0
#define OFF_B 16384
#define GEMM_SMEM (3 * STG_BYTES)    // 96 KB

__device__ __forceinline__ void gemm_load_stage(
    uint32_t sb, int stage,
    const __half* __restrict__ A, const __half* __restrict__ Bh,
    int row0, int col0, int kb, int K, int tid)
{
    uint32_t st = sb + stage * STG_BYTES;
    const int k0 = kb * 64;
#pragma unroll
    for (int u = 0; u < 4; u++) {
        int idx = u * 256 + tid;                 // 1024 16B chunks per operand
        int r = idx >> 3, c = idx & 7;
        uint32_t sw = (uint32_t)(r * 128 + ((c ^ (r & 7)) << 4));
        size_t ga = (size_t)(row0 + r) * K + k0 + c * 8;
        size_t gb = (size_t)(col0 + r) * K + k0 + c * 8;
        CP_ASYNC16(st + OFF_A + sw, A + ga);
        CP_ASYNC16(st + OFF_B + sw, Bh + gb);
    }
}

template<int OUT16>
__global__ void __launch_bounds__(256, 2) gemm_mma_kernel(
    const __half* __restrict__ A, const __half* __restrict__ Bh,
    float* __restrict__ Cout, __half* __restrict__ Cout16,
    const float* __restrict__ bias, int N, int K)
{
    extern __shared__ __align__(1024) char smem[];
    const uint32_t sb = smem_u32(smem);
    const int tid = threadIdx.x;
    const int wid = tid >> 5, lane = tid & 31;
    const int wr = wid >> 2, wc = wid & 3;       // warp grid 2 x 4
    const int col0 = blockIdx.x * 128;
    const int row0 = blockIdx.y * 128;
    const int NK = K / 64;

    float acc[4][4][4];
#pragma unroll
    for (int i = 0; i < 4; i++)
#pragma unroll
        for (int j = 0; j < 4; j++)
#pragma unroll
            for (int k = 0; k < 4; k++) acc[i][j][k] = 0.f;

    gemm_load_stage(sb, 0, A, Bh, row0, col0, 0, K, tid);
    CP_COMMIT();
    gemm_load_stage(sb, 1, A, Bh, row0, col0, 1, K, tid);
    CP_COMMIT();

    const int a_row = wr * 64 + (lane & 15);
    const int a_cg  = (lane >> 4);
    const int b_row = wc * 32 + (lane & 7) + ((lane >> 4) << 3);
    const int b_cg  = ((lane >> 3) & 1);

    int slot = 0, nslot = 2;
    for (int kb = 0; kb < NK; kb++) {
        CP_WAIT_GROUP(1);
        __syncthreads();
        if (kb + 2 < NK)
            gemm_load_stage(sb, nslot, A, Bh, row0, col0, kb + 2, K, tid);
        CP_COMMIT();

        uint32_t st = sb + slot * STG_BYTES;
#pragma unroll
        for (int ks = 0; ks < 4; ks++) {
            uint32_t af[4][4], bf[4][2];
#pragma unroll
            for (int mt = 0; mt < 4; mt++) {
                int r = a_row + mt * 16;
                int c = ks * 2 + a_cg;
                uint32_t ad = st + (uint32_t)(r * 128 + ((c ^ (r & 7)) << 4));
                LDMATRIX_X4(af[mt][0], af[mt][1], af[mt][2], af[mt][3], ad + OFF_A);
            }
#pragma unroll
            for (int ntp = 0; ntp < 2; ntp++) {
                int n = b_row + ntp * 16;
                int c = ks * 2 + b_cg;
                uint32_t bd = st + (uint32_t)(n * 128 + ((c ^ (n & 7)) << 4));
                LDMATRIX_X4(bf[2 * ntp][0], bf[2 * ntp][1],
                            bf[2 * ntp + 1][0], bf[2 * ntp + 1][1], bd + OFF_B);
            }
#pragma unroll
            for (int mt = 0; mt < 4; mt++)
#pragma unroll
                for (int nt = 0; nt < 4; nt++)
                    MMA_FP16(acc[mt][nt], af[mt], bf[nt]);
        }
        slot = (slot == 2) ? 0 : slot + 1;
        nslot = (nslot == 2) ? 0 : nslot + 1;
    }

    const int er = lane >> 2;
    const int ec = (lane & 3) * 2;
#pragma unroll
    for (int mt = 0; mt < 4; mt++) {
        int row = row0 + wr * 64 + mt * 16 + er;
#pragma unroll
        for (int nt = 0; nt < 4; nt++) {
            int col = col0 + wc * 32 + nt * 8 + ec;
            if (OUT16) {
                *(__half2*)&Cout16[(size_t)row * N + col] =
                    __floats2half2_rn(acc[mt][nt][0], acc[mt][nt][1]);
                *(__half2*)&Cout16[(size_t)(row + 8) * N + col] =
                    __floats2half2_rn(acc[mt][nt][2], acc[mt][nt][3]);
            } else {
                float b0 = 0.f, b1 = 0.f;
                if (bias) { b0 = bias[col]; b1 = bias[col + 1]; }
                float2 v0, v1;
                v0.x = acc[mt][nt][0] + b0; v0.y = acc[mt][nt][1] + b1;
                v1.x = acc[mt][nt][2] + b0; v1.y = acc[mt][nt][3] + b1;
                *(float2*)&Cout[(size_t)row * N + col] = v0;
                *(float2*)&Cout[(size_t)(row + 8) * N + col] = v1;
            }
        }
    }
}

// ---------------------------------------------------------------------------
// RoPE table
// ---------------------------------------------------------------------------
__global__ void rope_table_kernel()
{
    int g = blockIdx.x * blockDim.x + threadIdx.x;
    if (g >= T_ * 64) return;
    int t = g >> 6, i = g & 63;
    double invf = pow(10000.0, -(double)i / 64.0);
    float  angf = (float)t * (float)invf;
    double ang  = (double)angf;
    g_cos[g] = (float)cos(ang);
    g_sin[g] = (float)sin(ang);
}

// ---------------------------------------------------------------------------
// RoPE (vectorized 8 halves/thread): g_qkv16[B,T,3C] -> q/k/v fp16 [BH,T,D]
// ---------------------------------------------------------------------------
__global__ void __launch_bounds__(256) rope_kernel()
{
    int g = blockIdx.x * 256 + threadIdx.x;     // BH*T*16 threads
    int dv = (g & 15) * 8;                      // 0,8,...,120
    int t  = (g >> 4) & 2047;
    int bh = g >> 15;
    int b  = bh >> 4, h = bh & 15;

    size_t src  = ((size_t)(b * T_ + t)) * N3_ + h * D_ + dv;
    size_t srcp = src - dv + (dv ^ 64);

    uint4 qa = *(const uint4*)&g_qkv16[src];
    uint4 qb = *(const uint4*)&g_qkv16[srcp];
    uint4 ka = *(const uint4*)&g_qkv16[src + C_];
    uint4 kb = *(const uint4*)&g_qkv16[srcp + C_];
    uint4 va = *(const uint4*)&g_qkv16[src + 2 * C_];

    float sgn = (dv < 64) ? -1.f : 1.f;
    int i0 = dv & 63;
    const float* ct = g_cos + t * 64 + i0;
    const float* st = g_sin + t * 64 + i0;

    uint4 qo, ko;
    const uint32_t* qav = (const uint32_t*)&qa;
    const uint32_t* qbv = (const uint32_t*)&qb;
    const uint32_t* kav = (const uint32_t*)&ka;
    const uint32_t* kbv = (const uint32_t*)&kb;
    uint32_t* qov = (uint32_t*)&qo;
    uint32_t* kov = (uint32_t*)&ko;
#pragma unroll
    for (int j = 0; j < 4; j++) {
        __half2 qah = *(const __half2*)&qav[j];
        __half2 qbh = *(const __half2*)&qbv[j];
        __half2 kah = *(const __half2*)&kav[j];
        __half2 kbh = *(const __half2*)&kbv[j];
        float c0 = ct[2 * j], c1 = ct[2 * j + 1];
        float s0 = st[2 * j], s1 = st[2 * j + 1];
        float q0 = __low2float(qah) * c0 + sgn * __low2float(qbh) * s0;
        float q1 = __high2float(qah) * c1 + sgn * __high2float(qbh) * s1;
        float k0 = __low2float(kah) * c0 + sgn * __low2float(kbh) * s0;
        float k1 = __high2float(kah) * c1 + sgn * __high2float(kbh) * s1;
        __half2 qh = __floats2half2_rn(q0, q1);
        __half2 kh = __floats2half2_rn(k0, k1);
        qov[j] = *(uint32_t*)&qh;
        kov[j] = *(uint32_t*)&kh;
    }

    size_t dst = ((size_t)bh * T_ + t) * D_ + dv;
    *(uint4*)&gq_s[dst] = qo;
    *(uint4*)&gk_s[dst] = ko;
    *(uint4*)&gv_s[dst] = va;
}

// ---------------------------------------------------------------------------
// Flash attention (causal) on HMMA, fp16.  CTA = 64 q rows, 128 threads
// (4 warps x 16 rows), KV tile = 64 keys, 2-stage cp.async, smem 80 KB
// -> 2 CTAs/SM for cross-CTA tensor-pipe overlap. Q fragments hoisted.
// Softmax in base-2 domain.
// ---------------------------------------------------------------------------
#define KV_STG 32768                     // K 16K + V 16K
#define ATTN_SMEM (16384 + 2 * KV_STG)   // Q 16K + 2 KV stages = 80 KB

__device__ __forceinline__ void attn_load_kv(
    uint32_t skv, int stage,
    const __half* __restrict__ ks, const __half* __restrict__ vs,
    int k0, int tid)
{
    uint32_t st = skv + stage * KV_STG;
    const __half* srcs[2] = {ks, vs};
#pragma unroll
    for (int u = 0; u < 16; u++) {
        int idx = u * 128 + tid;
        int a = u >> 3;                     // 0=K, 1=V
        int rem = idx & 1023;
        int r = rem >> 4, c = rem & 15;
        uint32_t dst = st + a * 16384 + r * 256 + ((c ^ (r & 7)) << 4);
        CP_ASYNC16(dst, srcs[a] + (size_t)(k0 + r) * D_ + c * 8);
    }
}

__global__ void __launch_bounds__(128, 2) attn_mma_kernel()
{
    extern __shared__ __align__(1024) char smem[];
    const uint32_t sb = smem_u32(smem);
    const int tid = threadIdx.x;
    const int w = tid >> 5, lane = tid & 31;     // 4 warps
    const int g = lane >> 2, tig = lane & 3;
    const int qt = (int)gridDim.x - 1 - (int)blockIdx.x;   // heavy tiles first
    const int bh = blockIdx.y;
    const int q0 = qt * 64;
    const int NT = qt + 1;                                  // 64-key tiles

    const size_t hb = (size_t)bh * T_ * D_;
    const __half* Qs = gq_s + hb;
    const __half* Ks = gk_s + hb;
    const __half* Vs = gv_s + hb;

    const uint32_t sq = sb;
    const uint32_t skv = sb + 16384;

    // Load Q tile (64 rows); + KV stage 0 — one commit group
#pragma unroll
    for (int u = 0; u < 8; u++) {
        int idx = u * 128 + tid;
        int r = idx >> 4, c = idx & 15;
        uint32_t dst = sq + r * 256 + ((c ^ (r & 7)) << 4);
        CP_ASYNC16(dst, Qs + (size_t)(q0 + r) * D_ + c * 8);
    }
    attn_load_kv(skv, 0, Ks, Vs, 0, tid);
    CP_COMMIT();

    // Wait for Q + KV0, hoist Q fragments into registers (loop-invariant)
    CP_WAIT_GROUP(0);
    __syncthreads();
    uint32_t qf[8][4];
    {
        int qrow = w * 16 + (lane & 15);
#pragma unroll
        for (int ks = 0; ks < 8; ks++) {
            int qc = 2 * ks + (lane >> 4);
            uint32_t qa = sq + qrow * 256 + ((qc ^ (qrow & 7)) << 4);
            LDMATRIX_X4(qf[ks][0], qf[ks][1], qf[ks][2], qf[ks][3], qa);
        }
    }

    float O[16][4];
#pragma unroll
    for (int i = 0; i < 16; i++)
#pragma unroll
        for (int j = 0; j < 4; j++) O[i][j] = 0.f;
    float m0 = -1e30f, m1 = -1e30f, l0 = 0.f, l1 = 0.f;
    const float scale2 = 0.08838834764831845f * 1.4426950408889634f;
    const int row0 = q0 + w * 16 + g;
    const int row1 = row0 + 8;

    for (int kt = 0; kt < NT; kt++) {
        if (kt > 0) {
            CP_WAIT_GROUP(0);
            __syncthreads();
        }
        if (kt + 1 < NT)
            attn_load_kv(skv, (kt + 1) & 1, Ks, Vs, (kt + 1) * 64, tid);
        CP_COMMIT();
        const uint32_t sk = skv + (kt & 1) * KV_STG;

        // S = Q K^T  (64 q x 64 k)
        float S[8][4];
#pragma unroll
        for (int i = 0; i < 8; i++)
#pragma unroll
            for (int j = 0; j < 4; j++) S[i][j] = 0.f;

#pragma unroll
        for (int ks = 0; ks < 8; ks++) {
#pragma unroll
            for (int np = 0; np < 4; np++) {
                int kr = np * 16 + (lane & 7) + ((lane >> 4) << 3);
                int kc = 2 * ks + ((lane >> 3) & 1);
                uint32_t ka = sk + kr * 256 + ((kc ^ (kr & 7)) << 4);
                uint32_t kf[4];
                LDMATRIX_X4(kf[0], kf[1], kf[2], kf[3], ka);
                MMA_FP16(S[2 * np],     qf[ks], kf);
                MMA_FP16(S[2 * np + 1], qf[ks], kf + 2);
            }
        }

        // scale (base-2) + causal mask (diagonal tile only)
        const bool dom = (kt == qt);
#pragma unroll
        for (int nt = 0; nt < 8; nt++)
#pragma unroll
            for (int q = 0; q < 4; q++) {
                float v = S[nt][q] * scale2;
                if (dom) {
                    int col = kt * 64 + nt * 8 + 2 * tig + (q & 1);
                    int row = (q < 2) ? row0 : row1;
                    if (col > row) v = -1e30f;
                }
                S[nt][q] = v;
            }

        // online softmax (base-2)
        float mx0 = -1e30f, mx1 = -1e30f;
#pragma unroll
        for (int nt = 0; nt < 8; nt++) {
            mx0 = fmaxf(mx0, fmaxf(S[nt][0], S[nt][1]));
            mx1 = fmaxf(mx1, fmaxf(S[nt][2], S[nt][3]));
        }
        mx0 = fmaxf(mx0, __shfl_xor_sync(0xffffffffu, mx0, 1));
        mx0 = fmaxf(mx0, __shfl_xor_sync(0xffffffffu, mx0, 2));
        mx1 = fmaxf(mx1, __shfl_xor_sync(0xffffffffu, mx1, 1));
        mx1 = fmaxf(mx1, __shfl_xor_sync(0xffffffffu, mx1, 2));
        float mn0 = fmaxf(m0, mx0), mn1 = fmaxf(m1, mx1);
        float a0 = exp2f(m0 - mn0), a1 = exp2f(m1 - mn1);
        m0 = mn0; m1 = mn1;
        float s0 = 0.f, s1 = 0.f;
#pragma unroll
        for (int nt = 0; nt < 8; nt++) {
            S[nt][0] = exp2f(S[nt][0] - mn0); s0 += S[nt][0];
            S[nt][1] = exp2f(S[nt][1] - mn0); s0 += S[nt][1];
            S[nt][2] = exp2f(S[nt][2] - mn1); s1 += S[nt][2];
            S[nt][3] = exp2f(S[nt][3] - mn1); s1 += S[nt][3];
        }
        s0 += __shfl_xor_sync(0xffffffffu, s0, 1);
        s0 += __shfl_xor_sync(0xffffffffu, s0, 2);
        s1 += __shfl_xor_sync(0xffffffffu, s1, 1);
        s1 += __shfl_xor_sync(0xffffffffu, s1, 2);
        l0 = l0 * a0 + s0;
        l1 = l1 * a1 + s1;
#pragma unroll
        for (int nt = 0; nt < 16; nt++) {
            O[nt][0] *= a0; O[nt][1] *= a0;
            O[nt][2] *= a1; O[nt][3] *= a1;
        }

        // O += P V  (P fp16, V fp16; 64 keys)
#pragma unroll
        for (int j = 0; j < 4; j++) {
            uint32_t pa[4];
            {
                __half2 h;
                h = __floats2half2_rn(S[2 * j][0],     S[2 * j][1]);     pa[0] = *(uint32_t*)&h;
                h = __floats2half2_rn(S[2 * j][2],     S[2 * j][3]);     pa[1] = *(uint32_t*)&h;
                h = __floats2half2_rn(S[2 * j + 1][0], S[2 * j + 1][1]); pa[2] = *(uint32_t*)&h;
                h = __floats2half2_rn(S[2 * j + 1][2], S[2 * j + 1][3]); pa[3] = *(uint32_t*)&h;
            }
#pragma unroll
            for (int np = 0; np < 8; np++) {
                int vr = j * 16 + (lane & 15);
                int vc = 2 * np + (lane >> 4);
                uint32_t va = sk + 16384 + vr * 256 + ((vc ^ (vr & 7)) << 4);
                uint32_t vf[4];
                LDMATRIX_X4_T(vf[0], vf[1], vf[2], vf[3], va);
                MMA_FP16(O[2 * np],     pa, vf);
                MMA_FP16(O[2 * np + 1], pa, vf + 2);
            }
        }
    }

    // Epilogue: normalize, stage to smem (64 x 132 floats = 33 KB), write fp16
    __syncthreads();                          // all warps done with KV smem
    float li0 = 1.0f / l0, li1 = 1.0f / l1;
    float* stg = (float*)smem;
    {
        int r0l = w * 16 + g, r1l = r0l + 8;
#pragma unroll
        for (int nt = 0; nt < 16; nt++) {
            float2 v0 = make_float2(O[nt][0] * li0, O[nt][1] * li0);
            float2 v1 = make_float2(O[nt][2] * li1, O[nt][3] * li1);
            *(float2*)&stg[r0l * 132 + nt * 8 + 2 * tig] = v0;
            *(float2*)&stg[r1l * 132 + nt * 8 + 2 * tig] = v1;
        }
    }
    __syncthreads();
    {
        int r = tid >> 1, ch = (tid & 1) * 64;   // 64 rows, 128 threads
        int b = bh >> 4, h = bh & 15;
        size_t base = ((size_t)(b * T_ + q0 + r)) * C_ + h * 128 + ch;
#pragma unroll
        for (int c = 0; c < 64; c += 2) {
            float x = stg[r * 132 + ch + c], y = stg[r * 132 + ch + c + 1];
            *(__half2*)&gcx_s[base + c] = __floats2half2_rn(x, y);
        }
    }
}

// ---------------------------------------------------------------------------
extern "C" void kernel_launch(void* const* d_in, const int* in_sizes, int n_in,
                              void* d_out, int out_size)
{
    const float* x = nullptr; const float* w_qkv = nullptr;
    const float* w_proj = nullptr; const float* b_proj = nullptr;
    for (int i = 0; i < n_in; i++) {
        switch (in_sizes[i]) {
            case M_ * C_:  x      = (const float*)d_in[i]; break;
            case C_ * N3_: w_qkv  = (const float*)d_in[i]; break;
            case C_ * C_:  w_proj = (const float*)d_in[i]; break;
            case C_:       b_proj = (const float*)d_in[i]; break;
        }
    }
    float* out = (float*)d_out;

    void *p_qkv16, *p_x, *p_cx, *p_wq, *p_wp;
    cudaGetSymbolAddress(&p_qkv16, g_qkv16);
    cudaGetSymbolAddress(&p_x,   gx_s);
    cudaGetSymbolAddress(&p_cx,  gcx_s);
    cudaGetSymbolAddress(&p_wq,  gwq);
    cudaGetSymbolAddress(&p_wp,  gwp);

    cudaFuncSetAttribute(gemm_mma_kernel<0>,
                         cudaFuncAttributeMaxDynamicSharedMemorySize, GEMM_SMEM);
    cudaFuncSetAttribute(gemm_mma_kernel<1>,
                         cudaFuncAttributeMaxDynamicSharedMemorySize, GEMM_SMEM);
    cudaFuncSetAttribute(attn_mma_kernel,
                         cudaFuncAttributeMaxDynamicSharedMemorySize, ATTN_SMEM);

    // 1) operand prep
    rope_table_kernel<<<(T_ * 64 + 255) / 256, 256>>>();
    round_kernel<<<(M_ * C_ / 4 + 255) / 256, 256>>>(
        x, (__half*)p_x, M_ * C_ / 4);
    transpose_h_kernel<<<dim3(N3_ / 32, C_ / 32), dim3(32, 8)>>>(
        w_qkv, (__half*)p_wq, C_, N3_);
    transpose_h_kernel<<<dim3(C_ / 32, C_ / 32), dim3(32, 8)>>>(
        w_proj, (__half*)p_wp, C_, C_);

    // 2) QKV GEMM (HMMA fp16) -> fp16 output
    gemm_mma_kernel<1><<<dim3(N3_ / 128, M_ / 128), 256, GEMM_SMEM>>>(
        (const __half*)p_x, (const __half*)p_wq,
        nullptr, (__half*)p_qkv16, nullptr, N3_, C_);

    // 3) RoPE (vectorized) -> single fp16 q/k/v
    rope_kernel<<<(BH_ * T_ * 16) / 256, 256>>>();

    // 4) causal flash attention on HMMA (64 q rows/CTA, 2 CTAs/SM)
    attn_mma_kernel<<<dim3(T_ / 64, BH_), 128, ATTN_SMEM>>>();

    // 5) projection GEMM (HMMA fp16) + bias -> fp32 out
    gemm_mma_kernel<0><<<dim3(C_ / 128, M_ / 128), 256, GEMM_SMEM>>>(
        (const __half*)p_cx, (const __half*)p_wp,
        out, nullptr, b_proj, C_, C_);
}

// round 15
// speedup vs baseline: 1.1506x; 1.0003x over previous
#include <cuda_runtime.h>
#include <cuda_bf16.h>
#include <cuda_fp16.h>
#include <math.h>
#include <stdint.h>

// Problem constants
#define B_   4
#define T_   2048
#define C_   2048
#define H_   16
#define D_   128
#define BH_  (B_ * H_)        // 64
#define M_   (B_ * T_)        // 8192
#define N3_  (3 * C_)         // 6144

// ============================ helpers ======================================
__device__ __forceinline__ uint32_t smem_u32(const void* p) {
    uint32_t a;
    asm("{ .reg .u64 t; cvta.to.shared.u64 t, %1; cvt.u32.u64 %0, t; }"
        : "=r"(a) : "l"(p));
    return a;
}
#define CP_ASYNC16(saddr, gptr) \
    asm volatile("cp.async.cg.shared.global [%0], [%1], 16;" \
                 :: "r"(saddr), "l"(gptr) : "memory")
#define CP_COMMIT() asm volatile("cp.async.commit_group;" ::: "memory")
#define CP_WAIT_GROUP(n) asm volatile("cp.async.wait_group %0;" :: "n"(n) : "memory")

#define LDMATRIX_X4(r0, r1, r2, r3, addr) \
    asm volatile("ldmatrix.sync.aligned.m8n8.x4.shared.b16 {%0,%1,%2,%3}, [%4];" \
                 : "=r"(r0), "=r"(r1), "=r"(r2), "=r"(r3) : "r"(addr))
#define LDMATRIX_X4_T(r0, r1, r2, r3, addr) \
    asm volatile("ldmatrix.sync.aligned.m8n8.x4.trans.shared.b16 {%0,%1,%2,%3}, [%4];" \
                 : "=r"(r0), "=r"(r1), "=r"(r2), "=r"(r3) : "r"(addr))
#define MMA_FP16(c, a, b) \
    asm volatile("mma.sync.aligned.m16n8k16.row.col.f32.f16.f16.f32 " \
                 "{%0,%1,%2,%3}, {%4,%5,%6,%7}, {%8,%9}, {%0,%1,%2,%3};" \
                 : "+f"((c)[0]), "+f"((c)[1]), "+f"((c)[2]), "+f"((c)[3]) \
                 : "r"((a)[0]), "r"((a)[1]), "r"((a)[2]), "r"((a)[3]), \
                   "r"((b)[0]), "r"((b)[1]))

// ---------------- scratch (device globals; no allocation allowed) ----------
__device__ __half g_qkv16[M_ * N3_];       // [8192, 6144] fp16 (QKV pre-rope)
__device__ float g_cos[T_ * 64];
__device__ float g_sin[T_ * 64];
__device__ __half gx_s[M_ * C_];           // activations [M,K]
__device__ __half gcx_s[M_ * C_];          // ctx [M,K]
__device__ __half gwq[N3_ * C_];           // W_qkv^T [N,K]
__device__ __half gwp[C_ * C_];            // W_proj^T [N,K]
__device__ __half gq_s[BH_ * T_ * D_];
__device__ __half gk_s[BH_ * T_ * D_];
// V is read directly from g_qkv16 (no rope needed) — no gv buffer.

// ---------------------------------------------------------------------------
// round fp32 -> fp16, elementwise (vectorized by 4)
// ---------------------------------------------------------------------------
__global__ void __launch_bounds__(256) round_kernel(
    const float* __restrict__ in, __half* __restrict__ out16, int n4)
{
    int i = blockIdx.x * 256 + threadIdx.x;
    if (i >= n4) return;
    float4 v = ((const float4*)in)[i];
    __half2* hp = (__half2*)out16;
    hp[i * 2 + 0] = __floats2half2_rn(v.x, v.y);
    hp[i * 2 + 1] = __floats2half2_rn(v.z, v.w);
}

// ---------------------------------------------------------------------------
// transpose + round: W[K,N] fp32 -> Wh[N,K] fp16
// ---------------------------------------------------------------------------
__global__ void __launch_bounds__(256) transpose_h_kernel(
    const float* __restrict__ W, __half* __restrict__ Th, int K, int N)
{
    __shared__ float t[32][33];
    int bn = blockIdx.x * 32;
    int bk = blockIdx.y * 32;
    int x = threadIdx.x, y = threadIdx.y;       // 32 x 8
#pragma unroll
    for (int i = 0; i < 32; i += 8)
        t[y + i][x] = W[(size_t)(bk + y + i) * N + bn + x];
    __syncthreads();
#pragma unroll
    for (int i = 0; i < 32; i += 8) {
        float v = t[x][y + i];                  // = W[bk+x][bn+y+i]
        Th[(size_t)(bn + y + i) * K + bk + x] = __float2half_rn(v);
    }
}

// ---------------------------------------------------------------------------
// HMMA GEMM: C[M,N] = A[M,K] @ B[N,K]^T, plain fp16 x fp16, fp32 accum.
// CTA 128x128, BK=64, 3-stage cp.async (wait_group 1), 8 warps, 2 CTAs/SM.
// OUT16=0: fp32 epilogue (+bias). OUT16=1: fp16 epilogue (no bias).
// NOTE: unconditional CP_COMMIT per iteration is load-bearing for the
// wait_group(1) accounting. Kernel is at the 128-reg limit — do not add state.
// ---------------------------------------------------------------------------
#define STG_BYTES 32768              // A 16K + B 16K
#define OFF_A 0
#define OFF_B 16384
#define GEMM_SMEM (3 * STG_BYTES)    // 96 KB

__device__ __forceinline__ void gemm_load_stage(
    uint32_t sb, int stage,
    const __half* __restrict__ A, const __half* __restrict__ Bh,
    int row0, int col0, int kb, int K, int tid)
{
    uint32_t st = sb + stage * STG_BYTES;
    const int k0 = kb * 64;
#pragma unroll
    for (int u = 0; u < 4; u++) {
        int idx = u * 256 + tid;                 // 1024 16B chunks per operand
        int r = idx >> 3, c = idx & 7;
        uint32_t sw = (uint32_t)(r * 128 + ((c ^ (r & 7)) << 4));
        size_t ga = (size_t)(row0 + r) * K + k0 + c * 8;
        size_t gb = (size_t)(col0 + r) * K + k0 + c * 8;
        CP_ASYNC16(st + OFF_A + sw, A + ga);
        CP_ASYNC16(st + OFF_B + sw, Bh + gb);
    }
}

template<int OUT16>
__global__ void __launch_bounds__(256, 2) gemm_mma_kernel(
    const __half* __restrict__ A, const __half* __restrict__ Bh,
    float* __restrict__ Cout, __half* __restrict__ Cout16,
    const float* __restrict__ bias, int N, int K)
{
    extern __shared__ __align__(1024) char smem[];
    const uint32_t sb = smem_u32(smem);
    const int tid = threadIdx.x;
    const int wid = tid >> 5, lane = tid & 31;
    const int wr = wid >> 2, wc = wid & 3;       // warp grid 2 x 4
    const int col0 = blockIdx.x * 128;
    const int row0 = blockIdx.y * 128;
    const int NK = K / 64;

    float acc[4][4][4];
#pragma unroll
    for (int i = 0; i < 4; i++)
#pragma unroll
        for (int j = 0; j < 4; j++)
#pragma unroll
            for (int k = 0; k < 4; k++) acc[i][j][k] = 0.f;

    gemm_load_stage(sb, 0, A, Bh, row0, col0, 0, K, tid);
    CP_COMMIT();
    gemm_load_stage(sb, 1, A, Bh, row0, col0, 1, K, tid);
    CP_COMMIT();

    const int a_row = wr * 64 + (lane & 15);
    const int a_cg  = (lane >> 4);
    const int b_row = wc * 32 + (lane & 7) + ((lane >> 4) << 3);
    const int b_cg  = ((lane >> 3) & 1);

    int slot = 0, nslot = 2;
    for (int kb = 0; kb < NK; kb++) {
        CP_WAIT_GROUP(1);
        __syncthreads();
        if (kb + 2 < NK)
            gemm_load_stage(sb, nslot, A, Bh, row0, col0, kb + 2, K, tid);
        CP_COMMIT();

        uint32_t st = sb + slot * STG_BYTES;
#pragma unroll
        for (int ks = 0; ks < 4; ks++) {
            uint32_t af[4][4], bf[4][2];
#pragma unroll
            for (int mt = 0; mt < 4; mt++) {
                int r = a_row + mt * 16;
                int c = ks * 2 + a_cg;
                uint32_t ad = st + (uint32_t)(r * 128 + ((c ^ (r & 7)) << 4));
                LDMATRIX_X4(af[mt][0], af[mt][1], af[mt][2], af[mt][3], ad + OFF_A);
            }
#pragma unroll
            for (int ntp = 0; ntp < 2; ntp++) {
                int n = b_row + ntp * 16;
                int c = ks * 2 + b_cg;
                uint32_t bd = st + (uint32_t)(n * 128 + ((c ^ (n & 7)) << 4));
                LDMATRIX_X4(bf[2 * ntp][0], bf[2 * ntp][1],
                            bf[2 * ntp + 1][0], bf[2 * ntp + 1][1], bd + OFF_B);
            }
#pragma unroll
            for (int mt = 0; mt < 4; mt++)
#pragma unroll
                for (int nt = 0; nt < 4; nt++)
                    MMA_FP16(acc[mt][nt], af[mt], bf[nt]);
        }
        slot = (slot == 2) ? 0 : slot + 1;
        nslot = (nslot == 2) ? 0 : nslot + 1;
    }

    const int er = lane >> 2;
    const int ec = (lane & 3) * 2;
#pragma unroll
    for (int mt = 0; mt < 4; mt++) {
        int row = row0 + wr * 64 + mt * 16 + er;
#pragma unroll
        for (int nt = 0; nt < 4; nt++) {
            int col = col0 + wc * 32 + nt * 8 + ec;
            if (OUT16) {
                *(__half2*)&Cout16[(size_t)row * N + col] =
                    __floats2half2_rn(acc[mt][nt][0], acc[mt][nt][1]);
                *(__half2*)&Cout16[(size_t)(row + 8) * N + col] =
                    __floats2half2_rn(acc[mt][nt][2], acc[mt][nt][3]);
            } else {
                float b0 = 0.f, b1 = 0.f;
                if (bias) { b0 = bias[col]; b1 = bias[col + 1]; }
                float2 v0, v1;
                v0.x = acc[mt][nt][0] + b0; v0.y = acc[mt][nt][1] + b1;
                v1.x = acc[mt][nt][2] + b0; v1.y = acc[mt][nt][3] + b1;
                *(float2*)&Cout[(size_t)row * N + col] = v0;
                *(float2*)&Cout[(size_t)(row + 8) * N + col] = v1;
            }
        }
    }
}

// ---------------------------------------------------------------------------
// RoPE table
// ---------------------------------------------------------------------------
__global__ void rope_table_kernel()
{
    int g = blockIdx.x * blockDim.x + threadIdx.x;
    if (g >= T_ * 64) return;
    int t = g >> 6, i = g & 63;
    double invf = pow(10000.0, -(double)i / 64.0);
    float  angf = (float)t * (float)invf;
    double ang  = (double)angf;
    g_cos[g] = (float)cos(ang);
    g_sin[g] = (float)sin(ang);
}

// ---------------------------------------------------------------------------
// RoPE (vectorized, q/k only): g_qkv16[B,T,3C] -> q/k fp16 [BH,T,D]
// V stays in g_qkv16 — attention reads it there directly.
// ---------------------------------------------------------------------------
__global__ void __launch_bounds__(256) rope_kernel()
{
    int g = blockIdx.x * 256 + threadIdx.x;     // BH*T*16 threads
    int dv = (g & 15) * 8;                      // 0,8,...,120
    int t  = (g >> 4) & 2047;
    int bh = g >> 15;
    int b  = bh >> 4, h = bh & 15;

    size_t src  = ((size_t)(b * T_ + t)) * N3_ + h * D_ + dv;
    size_t srcp = src - dv + (dv ^ 64);

    uint4 qa = *(const uint4*)&g_qkv16[src];
    uint4 qb = *(const uint4*)&g_qkv16[srcp];
    uint4 ka = *(const uint4*)&g_qkv16[src + C_];
    uint4 kb = *(const uint4*)&g_qkv16[srcp + C_];

    float sgn = (dv < 64) ? -1.f : 1.f;
    int i0 = dv & 63;
    const float* ct = g_cos + t * 64 + i0;
    const float* st = g_sin + t * 64 + i0;

    uint4 qo, ko;
    const uint32_t* qav = (const uint32_t*)&qa;
    const uint32_t* qbv = (const uint32_t*)&qb;
    const uint32_t* kav = (const uint32_t*)&ka;
    const uint32_t* kbv = (const uint32_t*)&kb;
    uint32_t* qov = (uint32_t*)&qo;
    uint32_t* kov = (uint32_t*)&ko;
#pragma unroll
    for (int j = 0; j < 4; j++) {
        __half2 qah = *(const __half2*)&qav[j];
        __half2 qbh = *(const __half2*)&qbv[j];
        __half2 kah = *(const __half2*)&kav[j];
        __half2 kbh = *(const __half2*)&kbv[j];
        float c0 = ct[2 * j], c1 = ct[2 * j + 1];
        float s0 = st[2 * j], s1 = st[2 * j + 1];
        float q0 = __low2float(qah) * c0 + sgn * __low2float(qbh) * s0;
        float q1 = __high2float(qah) * c1 + sgn * __high2float(qbh) * s1;
        float k0 = __low2float(kah) * c0 + sgn * __low2float(kbh) * s0;
        float k1 = __high2float(kah) * c1 + sgn * __high2float(kbh) * s1;
        __half2 qh = __floats2half2_rn(q0, q1);
        __half2 kh = __floats2half2_rn(k0, k1);
        qov[j] = *(uint32_t*)&qh;
        kov[j] = *(uint32_t*)&kh;
    }

    size_t dst = ((size_t)bh * T_ + t) * D_ + dv;
    *(uint4*)&gq_s[dst] = qo;
    *(uint4*)&gk_s[dst] = ko;
}

// ---------------------------------------------------------------------------
// Flash attention (causal) on HMMA, fp16.  CTA = 64 q rows, 128 threads
// (4 warps x 16 rows), KV tile = 64 keys, 2-stage cp.async, smem 80 KB
// -> 2 CTAs/SM. Q fragments hoisted. Softmax in base-2 domain.
// V is read straight from g_qkv16 (row stride N3_).
// ---------------------------------------------------------------------------
#define KV_STG 32768                     // K 16K + V 16K
#define ATTN_SMEM (16384 + 2 * KV_STG)   // Q 16K + 2 KV stages = 80 KB

__device__ __forceinline__ void attn_load_kv(
    uint32_t skv, int stage,
    const __half* __restrict__ ks, const __half* __restrict__ vs,
    int k0, int tid)
{
    uint32_t st = skv + stage * KV_STG;
#pragma unroll
    for (int u = 0; u < 16; u++) {
        int idx = u * 128 + tid;
        int a = u >> 3;                     // 0=K (stride D_), 1=V (stride N3_)
        int rem = idx & 1023;
        int r = rem >> 4, c = rem & 15;
        uint32_t dst = st + a * 16384 + r * 256 + ((c ^ (r & 7)) << 4);
        if (a == 0)
            CP_ASYNC16(dst, ks + (size_t)(k0 + r) * D_ + c * 8);
        else
            CP_ASYNC16(dst, vs + (size_t)(k0 + r) * N3_ + c * 8);
    }
}

__global__ void __launch_bounds__(128, 2) attn_mma_kernel()
{
    extern __shared__ __align__(1024) char smem[];
    const uint32_t sb = smem_u32(smem);
    const int tid = threadIdx.x;
    const int w = tid >> 5, lane = tid & 31;     // 4 warps
    const int g = lane >> 2, tig = lane & 3;
    const int qt = (int)gridDim.x - 1 - (int)blockIdx.x;   // heavy tiles first
    const int bh = blockIdx.y;
    const int b = bh >> 4, h = bh & 15;
    const int q0 = qt * 64;
    const int NT = qt + 1;                                  // 64-key tiles

    const size_t hb = (size_t)bh * T_ * D_;
    const __half* Qs = gq_s + hb;
    const __half* Ks = gk_s + hb;
    // V directly from g_qkv16: row t at (b*T + t)*N3 + 2C + h*128
    const __half* Vs = g_qkv16 + (size_t)(b * T_) * N3_ + 2 * C_ + h * D_;

    const uint32_t sq = sb;
    const uint32_t skv = sb + 16384;

    // Load Q tile (64 rows); + KV stage 0 — one commit group
#pragma unroll
    for (int u = 0; u < 8; u++) {
        int idx = u * 128 + tid;
        int r = idx >> 4, c = idx & 15;
        uint32_t dst = sq + r * 256 + ((c ^ (r & 7)) << 4);
        CP_ASYNC16(dst, Qs + (size_t)(q0 + r) * D_ + c * 8);
    }
    attn_load_kv(skv, 0, Ks, Vs, 0, tid);
    CP_COMMIT();

    // Wait for Q + KV0, hoist Q fragments into registers (loop-invariant)
    CP_WAIT_GROUP(0);
    __syncthreads();
    uint32_t qf[8][4];
    {
        int qrow = w * 16 + (lane & 15);
#pragma unroll
        for (int ks = 0; ks < 8; ks++) {
            int qc = 2 * ks + (lane >> 4);
            uint32_t qa = sq + qrow * 256 + ((qc ^ (qrow & 7)) << 4);
            LDMATRIX_X4(qf[ks][0], qf[ks][1], qf[ks][2], qf[ks][3], qa);
        }
    }

    float O[16][4];
#pragma unroll
    for (int i = 0; i < 16; i++)
#pragma unroll
        for (int j = 0; j < 4; j++) O[i][j] = 0.f;
    float m0 = -1e30f, m1 = -1e30f, l0 = 0.f, l1 = 0.f;
    const float scale2 = 0.08838834764831845f * 1.4426950408889634f;
    const int row0 = q0 + w * 16 + g;
    const int row1 = row0 + 8;

    for (int kt = 0; kt < NT; kt++) {
        if (kt > 0) {
            CP_WAIT_GROUP(0);
            __syncthreads();
        }
        if (kt + 1 < NT)
            attn_load_kv(skv, (kt + 1) & 1, Ks, Vs, (kt + 1) * 64, tid);
        CP_COMMIT();
        const uint32_t sk = skv + (kt & 1) * KV_STG;

        // S = Q K^T  (64 q x 64 k)
        float S[8][4];
#pragma unroll
        for (int i = 0; i < 8; i++)
#pragma unroll
            for (int j = 0; j < 4; j++) S[i][j] = 0.f;

#pragma unroll
        for (int ks = 0; ks < 8; ks++) {
#pragma unroll
            for (int np = 0; np < 4; np++) {
                int kr = np * 16 + (lane & 7) + ((lane >> 4) << 3);
                int kc = 2 * ks + ((lane >> 3) & 1);
                uint32_t ka = sk + kr * 256 + ((kc ^ (kr & 7)) << 4);
                uint32_t kf[4];
                LDMATRIX_X4(kf[0], kf[1], kf[2], kf[3], ka);
                MMA_FP16(S[2 * np],     qf[ks], kf);
                MMA_FP16(S[2 * np + 1], qf[ks], kf + 2);
            }
        }

        // scale (base-2) + causal mask (diagonal tile only)
        const bool dom = (kt == qt);
#pragma unroll
        for (int nt = 0; nt < 8; nt++)
#pragma unroll
            for (int q = 0; q < 4; q++) {
                float v = S[nt][q] * scale2;
                if (dom) {
                    int col = kt * 64 + nt * 8 + 2 * tig + (q & 1);
                    int row = (q < 2) ? row0 : row1;
                    if (col > row) v = -1e30f;
                }
                S[nt][q] = v;
            }

        // online softmax (base-2)
        float mx0 = -1e30f, mx1 = -1e30f;
#pragma unroll
        for (int nt = 0; nt < 8; nt++) {
            mx0 = fmaxf(mx0, fmaxf(S[nt][0], S[nt][1]));
            mx1 = fmaxf(mx1, fmaxf(S[nt][2], S[nt][3]));
        }
        mx0 = fmaxf(mx0, __shfl_xor_sync(0xffffffffu, mx0, 1));
        mx0 = fmaxf(mx0, __shfl_xor_sync(0xffffffffu, mx0, 2));
        mx1 = fmaxf(mx1, __shfl_xor_sync(0xffffffffu, mx1, 1));
        mx1 = fmaxf(mx1, __shfl_xor_sync(0xffffffffu, mx1, 2));
        float mn0 = fmaxf(m0, mx0), mn1 = fmaxf(m1, mx1);
        float a0 = exp2f(m0 - mn0), a1 = exp2f(m1 - mn1);
        m0 = mn0; m1 = mn1;
        float s0 = 0.f, s1 = 0.f;
#pragma unroll
        for (int nt = 0; nt < 8; nt++) {
            S[nt][0] = exp2f(S[nt][0] - mn0); s0 += S[nt][0];
            S[nt][1] = exp2f(S[nt][1] - mn0); s0 += S[nt][1];
            S[nt][2] = exp2f(S[nt][2] - mn1); s1 += S[nt][2];
            S[nt][3] = exp2f(S[nt][3] - mn1); s1 += S[nt][3];
        }
        s0 += __shfl_xor_sync(0xffffffffu, s0, 1);
        s0 += __shfl_xor_sync(0xffffffffu, s0, 2);
        s1 += __shfl_xor_sync(0xffffffffu, s1, 1);
        s1 += __shfl_xor_sync(0xffffffffu, s1, 2);
        l0 = l0 * a0 + s0;
        l1 = l1 * a1 + s1;
#pragma unroll
        for (int nt = 0; nt < 16; nt++) {
            O[nt][0] *= a0; O[nt][1] *= a0;
            O[nt][2] *= a1; O[nt][3] *= a1;
        }

        // O += P V  (P fp16, V fp16; 64 keys)
#pragma unroll
        for (int j = 0; j < 4; j++) {
            uint32_t pa[4];
            {
                __half2 h2v;
                h2v = __floats2half2_rn(S[2 * j][0],     S[2 * j][1]);     pa[0] = *(uint32_t*)&h2v;
                h2v = __floats2half2_rn(S[2 * j][2],     S[2 * j][3]);     pa[1] = *(uint32_t*)&h2v;
                h2v = __floats2half2_rn(S[2 * j + 1][0], S[2 * j + 1][1]); pa[2] = *(uint32_t*)&h2v;
                h2v = __floats2half2_rn(S[2 * j + 1][2], S[2 * j + 1][3]); pa[3] = *(uint32_t*)&h2v;
            }
#pragma unroll
            for (int np = 0; np < 8; np++) {
                int vr = j * 16 + (lane & 15);
                int vc = 2 * np + (lane >> 4);
                uint32_t va = sk + 16384 + vr * 256 + ((vc ^ (vr & 7)) << 4);
                uint32_t vf[4];
                LDMATRIX_X4_T(vf[0], vf[1], vf[2], vf[3], va);
                MMA_FP16(O[2 * np],     pa, vf);
                MMA_FP16(O[2 * np + 1], pa, vf + 2);
            }
        }
    }

    // Epilogue: normalize, stage to smem (64 x 132 floats = 33 KB), write fp16
    __syncthreads();                          // all warps done with KV smem
    float li0 = 1.0f / l0, li1 = 1.0f / l1;
    float* stg = (float*)smem;
    {
        int r0l = w * 16 + g, r1l = r0l + 8;
#pragma unroll
        for (int nt = 0; nt < 16; nt++) {
            float2 v0 = make_float2(O[nt][0] * li0, O[nt][1] * li0);
            float2 v1 = make_float2(O[nt][2] * li1, O[nt][3] * li1);
            *(float2*)&stg[r0l * 132 + nt * 8 + 2 * tig] = v0;
            *(float2*)&stg[r1l * 132 + nt * 8 + 2 * tig] = v1;
        }
    }
    __syncthreads();
    {
        int r = tid >> 1, ch = (tid & 1) * 64;   // 64 rows, 128 threads
        size_t base = ((size_t)(b * T_ + q0 + r)) * C_ + h * 128 + ch;
#pragma unroll
        for (int c = 0; c < 64; c += 2) {
            float x = stg[r * 132 + ch + c], y = stg[r * 132 + ch + c + 1];
            *(__half2*)&gcx_s[base + c] = __floats2half2_rn(x, y);
        }
    }
}

// ---------------------------------------------------------------------------
extern "C" void kernel_launch(void* const* d_in, const int* in_sizes, int n_in,
                              void* d_out, int out_size)
{
    const float* x = nullptr; const float* w_qkv = nullptr;
    const float* w_proj = nullptr; const float* b_proj = nullptr;
    for (int i = 0; i < n_in; i++) {
        switch (in_sizes[i]) {
            case M_ * C_:  x      = (const float*)d_in[i]; break;
            case C_ * N3_: w_qkv  = (const float*)d_in[i]; break;
            case C_ * C_:  w_proj = (const float*)d_in[i]; break;
            case C_:       b_proj = (const float*)d_in[i]; break;
        }
    }
    float* out = (float*)d_out;

    void *p_qkv16, *p_x, *p_cx, *p_wq, *p_wp;
    cudaGetSymbolAddress(&p_qkv16, g_qkv16);
    cudaGetSymbolAddress(&p_x,   gx_s);
    cudaGetSymbolAddress(&p_cx,  gcx_s);
    cudaGetSymbolAddress(&p_wq,  gwq);
    cudaGetSymbolAddress(&p_wp,  gwp);

    cudaFuncSetAttribute(gemm_mma_kernel<0>,
                         cudaFuncAttributeMaxDynamicSharedMemorySize, GEMM_SMEM);
    cudaFuncSetAttribute(gemm_mma_kernel<1>,
                         cudaFuncAttributeMaxDynamicSharedMemorySize, GEMM_SMEM);
    cudaFuncSetAttribute(attn_mma_kernel,
                         cudaFuncAttributeMaxDynamicSharedMemorySize, ATTN_SMEM);

    // 1) operand prep
    rope_table_kernel<<<(T_ * 64 + 255) / 256, 256>>>();
    round_kernel<<<(M_ * C_ / 4 + 255) / 256, 256>>>(
        x, (__half*)p_x, M_ * C_ / 4);
    transpose_h_kernel<<<dim3(N3_ / 32, C_ / 32), dim3(32, 8)>>>(
        w_qkv, (__half*)p_wq, C_, N3_);
    transpose_h_kernel<<<dim3(C_ / 32, C_ / 32), dim3(32, 8)>>>(
        w_proj, (__half*)p_wp, C_, C_);

    // 2) QKV GEMM (HMMA fp16) -> fp16 output
    gemm_mma_kernel<1><<<dim3(N3_ / 128, M_ / 128), 256, GEMM_SMEM>>>(
        (const __half*)p_x, (const __half*)p_wq,
        nullptr, (__half*)p_qkv16, nullptr, N3_, C_);

    // 3) RoPE (q/k only) -> fp16 [BH,T,D]
    rope_kernel<<<(BH_ * T_ * 16) / 256, 256>>>();

    // 4) causal flash attention (V read directly from g_qkv16)
    attn_mma_kernel<<<dim3(T_ / 64, BH_), 128, ATTN_SMEM>>>();

    // 5) projection GEMM (HMMA fp16) + bias -> fp32 out
    gemm_mma_kernel<0><<<dim3(C_ / 128, M_ / 128), 256, GEMM_SMEM>>>(
        (const __half*)p_cx, (const __half*)p_wp,
        out, nullptr, b_proj, C_, C_);
}

// round 16
// speedup vs baseline: 1.1593x; 1.0075x over previous
#include <cuda_runtime.h>
#include <cuda_bf16.h>
#include <cuda_fp16.h>
#include <math.h>
#include <stdint.h>

// Problem constants
#define B_   4
#define T_   2048
#define C_   2048
#define H_   16
#define D_   128
#define BH_  (B_ * H_)        // 64
#define M_   (B_ * T_)        // 8192
#define N3_  (3 * C_)         // 6144

// ============================ helpers ======================================
__device__ __forceinline__ uint32_t smem_u32(const void* p) {
    uint32_t a;
    asm("{ .reg .u64 t; cvta.to.shared.u64 t, %1; cvt.u32.u64 %0, t; }"
        : "=r"(a) : "l"(p));
    return a;
}
#define CP_ASYNC16(saddr, gptr) \
    asm volatile("cp.async.cg.shared.global [%0], [%1], 16;" \
                 :: "r"(saddr), "l"(gptr) : "memory")
#define CP_COMMIT() asm volatile("cp.async.commit_group;" ::: "memory")
#define CP_WAIT_GROUP(n) asm volatile("cp.async.wait_group %0;" :: "n"(n) : "memory")

#define LDMATRIX_X4(r0, r1, r2, r3, addr) \
    asm volatile("ldmatrix.sync.aligned.m8n8.x4.shared.b16 {%0,%1,%2,%3}, [%4];" \
                 : "=r"(r0), "=r"(r1), "=r"(r2), "=r"(r3) : "r"(addr))
#define LDMATRIX_X4_T(r0, r1, r2, r3, addr) \
    asm volatile("ldmatrix.sync.aligned.m8n8.x4.trans.shared.b16 {%0,%1,%2,%3}, [%4];" \
                 : "=r"(r0), "=r"(r1), "=r"(r2), "=r"(r3) : "r"(addr))
#define MMA_FP16(c, a, b) \
    asm volatile("mma.sync.aligned.m16n8k16.row.col.f32.f16.f16.f32 " \
                 "{%0,%1,%2,%3}, {%4,%5,%6,%7}, {%8,%9}, {%0,%1,%2,%3};" \
                 : "+f"((c)[0]), "+f"((c)[1]), "+f"((c)[2]), "+f"((c)[3]) \
                 : "r"((a)[0]), "r"((a)[1]), "r"((a)[2]), "r"((a)[3]), \
                   "r"((b)[0]), "r"((b)[1]))

// ---------------- scratch (device globals; no allocation allowed) ----------
__device__ __half g_qkv16[M_ * N3_];       // [8192, 6144] fp16 (QKV pre-rope)
__device__ float g_cos[T_ * 64];
__device__ float g_sin[T_ * 64];
__device__ __half gx_s[M_ * C_];           // activations [M,K]
__device__ __half gcx_s[M_ * C_];          // ctx [M,K]
__device__ __half gwq[N3_ * C_];           // W_qkv^T [N,K]
__device__ __half gwp[C_ * C_];            // W_proj^T [N,K]
__device__ __half gq_s[BH_ * T_ * D_];
__device__ __half gk_s[BH_ * T_ * D_];
// V is read directly from g_qkv16 (no rope needed) — no gv buffer.

// ---------------------------------------------------------------------------
// Fused prep: one launch dispatching four independent workloads by blockIdx.
//  [0, 16384)       : round x fp32 -> gx_s fp16 (float4 per thread)
//  [16384, 28672)   : transpose+round w_qkv -> gwq  (12288 tiles of 32x32)
//  [28672, 32768)   : transpose+round w_proj -> gwp (4096 tiles)
//  [32768, 33280)   : RoPE cos/sin table
// Bitwise-identical outputs to the previous four kernels.
// ---------------------------------------------------------------------------
#define PREP_GRID 33280

__global__ void __launch_bounds__(256) prep_kernel(
    const float* __restrict__ x, const float* __restrict__ wqv,
    const float* __restrict__ wpr)
{
    __shared__ float t[32][33];
    const int bid = blockIdx.x;
    const int tid = threadIdx.x;

    if (bid < 16384) {
        // ---- round activations ----
        int i = bid * 256 + tid;                 // exactly covers M_*C_/4
        float4 v = ((const float4*)x)[i];
        __half2* hp = (__half2*)gx_s;
        hp[i * 2 + 0] = __floats2half2_rn(v.x, v.y);
        hp[i * 2 + 1] = __floats2half2_rn(v.z, v.w);
    } else if (bid < 32768) {
        // ---- weight transposes ----
        const float* W; __half* Th; int N; int idx;
        if (bid < 28672) { W = wqv; Th = gwq; N = N3_; idx = bid - 16384; }
        else             { W = wpr; Th = gwp; N = C_;  idx = bid - 28672; }
        const int K = C_;
        const int ntx = N / 32;
        const int bn = (idx % ntx) * 32;
        const int bk = (idx / ntx) * 32;
        const int xx = tid & 31, yy = tid >> 5;   // 32 x 8
#pragma unroll
        for (int i = 0; i < 32; i += 8)
            t[yy + i][xx] = W[(size_t)(bk + yy + i) * N + bn + xx];
        __syncthreads();
#pragma unroll
        for (int i = 0; i < 32; i += 8) {
            float v = t[xx][yy + i];
            Th[(size_t)(bn + yy + i) * K + bk + xx] = __float2half_rn(v);
        }
    } else {
        // ---- RoPE table ----
        int g = (bid - 32768) * 256 + tid;
        if (g < T_ * 64) {
            int tt = g >> 6, ii = g & 63;
            double invf = pow(10000.0, -(double)ii / 64.0);
            float  angf = (float)tt * (float)invf;
            double ang  = (double)angf;
            g_cos[g] = (float)cos(ang);
            g_sin[g] = (float)sin(ang);
        }
    }
}

// ---------------------------------------------------------------------------
// HMMA GEMM: C[M,N] = A[M,K] @ B[N,K]^T, plain fp16 x fp16, fp32 accum.
// CTA 128x128, BK=64, 3-stage cp.async (wait_group 1), 8 warps, 2 CTAs/SM.
// OUT16=0: fp32 epilogue (+bias). OUT16=1: fp16 epilogue (no bias).
// NOTE: unconditional CP_COMMIT per iteration is load-bearing for the
// wait_group(1) accounting. Kernel is at the 128-reg limit — do not add state.
// ---------------------------------------------------------------------------
#define STG_BYTES 32768              // A 16K + B 16K
#define OFF_A 0
#define OFF_B 16384
#define GEMM_SMEM (3 * STG_BYTES)    // 96 KB

__device__ __forceinline__ void gemm_load_stage(
    uint32_t sb, int stage,
    const __half* __restrict__ A, const __half* __restrict__ Bh,
    int row0, int col0, int kb, int K, int tid)
{
    uint32_t st = sb + stage * STG_BYTES;
    const int k0 = kb * 64;
#pragma unroll
    for (int u = 0; u < 4; u++) {
        int idx = u * 256 + tid;                 // 1024 16B chunks per operand
        int r = idx >> 3, c = idx & 7;
        uint32_t sw = (uint32_t)(r * 128 + ((c ^ (r & 7)) << 4));
        size_t ga = (size_t)(row0 + r) * K + k0 + c * 8;
        size_t gb = (size_t)(col0 + r) * K + k0 + c * 8;
        CP_ASYNC16(st + OFF_A + sw, A + ga);
        CP_ASYNC16(st + OFF_B + sw, Bh + gb);
    }
}

template<int OUT16>
__global__ void __launch_bounds__(256, 2) gemm_mma_kernel(
    const __half* __restrict__ A, const __half* __restrict__ Bh,
    float* __restrict__ Cout, __half* __restrict__ Cout16,
    const float* __restrict__ bias, int N, int K)
{
    extern __shared__ __align__(1024) char smem[];
    const uint32_t sb = smem_u32(smem);
    const int tid = threadIdx.x;
    const int wid = tid >> 5, lane = tid & 31;
    const int wr = wid >> 2, wc = wid & 3;       // warp grid 2 x 4
    const int col0 = blockIdx.x * 128;
    const int row0 = blockIdx.y * 128;
    const int NK = K / 64;

    float acc[4][4][4];
#pragma unroll
    for (int i = 0; i < 4; i++)
#pragma unroll
        for (int j = 0; j < 4; j++)
#pragma unroll
            for (int k = 0; k < 4; k++) acc[i][j][k] = 0.f;

    gemm_load_stage(sb, 0, A, Bh, row0, col0, 0, K, tid);
    CP_COMMIT();
    gemm_load_stage(sb, 1, A, Bh, row0, col0, 1, K, tid);
    CP_COMMIT();

    const int a_row = wr * 64 + (lane & 15);
    const int a_cg  = (lane >> 4);
    const int b_row = wc * 32 + (lane & 7) + ((lane >> 4) << 3);
    const int b_cg  = ((lane >> 3) & 1);

    int slot = 0, nslot = 2;
    for (int kb = 0; kb < NK; kb++) {
        CP_WAIT_GROUP(1);
        __syncthreads();
        if (kb + 2 < NK)
            gemm_load_stage(sb, nslot, A, Bh, row0, col0, kb + 2, K, tid);
        CP_COMMIT();

        uint32_t st = sb + slot * STG_BYTES;
#pragma unroll
        for (int ks = 0; ks < 4; ks++) {
            uint32_t af[4][4], bf[4][2];
#pragma unroll
            for (int mt = 0; mt < 4; mt++) {
                int r = a_row + mt * 16;
                int c = ks * 2 + a_cg;
                uint32_t ad = st + (uint32_t)(r * 128 + ((c ^ (r & 7)) << 4));
                LDMATRIX_X4(af[mt][0], af[mt][1], af[mt][2], af[mt][3], ad + OFF_A);
            }
#pragma unroll
            for (int ntp = 0; ntp < 2; ntp++) {
                int n = b_row + ntp * 16;
                int c = ks * 2 + b_cg;
                uint32_t bd = st + (uint32_t)(n * 128 + ((c ^ (n & 7)) << 4));
                LDMATRIX_X4(bf[2 * ntp][0], bf[2 * ntp][1],
                            bf[2 * ntp + 1][0], bf[2 * ntp + 1][1], bd + OFF_B);
            }
#pragma unroll
            for (int mt = 0; mt < 4; mt++)
#pragma unroll
                for (int nt = 0; nt < 4; nt++)
                    MMA_FP16(acc[mt][nt], af[mt], bf[nt]);
        }
        slot = (slot == 2) ? 0 : slot + 1;
        nslot = (nslot == 2) ? 0 : nslot + 1;
    }

    const int er = lane >> 2;
    const int ec = (lane & 3) * 2;
#pragma unroll
    for (int mt = 0; mt < 4; mt++) {
        int row = row0 + wr * 64 + mt * 16 + er;
#pragma unroll
        for (int nt = 0; nt < 4; nt++) {
            int col = col0 + wc * 32 + nt * 8 + ec;
            if (OUT16) {
                *(__half2*)&Cout16[(size_t)row * N + col] =
                    __floats2half2_rn(acc[mt][nt][0], acc[mt][nt][1]);
                *(__half2*)&Cout16[(size_t)(row + 8) * N + col] =
                    __floats2half2_rn(acc[mt][nt][2], acc[mt][nt][3]);
            } else {
                float b0 = 0.f, b1 = 0.f;
                if (bias) { b0 = bias[col]; b1 = bias[col + 1]; }
                float2 v0, v1;
                v0.x = acc[mt][nt][0] + b0; v0.y = acc[mt][nt][1] + b1;
                v1.x = acc[mt][nt][2] + b0; v1.y = acc[mt][nt][3] + b1;
                *(float2*)&Cout[(size_t)row * N + col] = v0;
                *(float2*)&Cout[(size_t)(row + 8) * N + col] = v1;
            }
        }
    }
}

// ---------------------------------------------------------------------------
// RoPE (vectorized, q/k only): g_qkv16[B,T,3C] -> q/k fp16 [BH,T,D]
// V stays in g_qkv16 — attention reads it there directly.
// ---------------------------------------------------------------------------
__global__ void __launch_bounds__(256) rope_kernel()
{
    int g = blockIdx.x * 256 + threadIdx.x;     // BH*T*16 threads
    int dv = (g & 15) * 8;                      // 0,8,...,120
    int t  = (g >> 4) & 2047;
    int bh = g >> 15;
    int b  = bh >> 4, h = bh & 15;

    size_t src  = ((size_t)(b * T_ + t)) * N3_ + h * D_ + dv;
    size_t srcp = src - dv + (dv ^ 64);

    uint4 qa = *(const uint4*)&g_qkv16[src];
    uint4 qb = *(const uint4*)&g_qkv16[srcp];
    uint4 ka = *(const uint4*)&g_qkv16[src + C_];
    uint4 kb = *(const uint4*)&g_qkv16[srcp + C_];

    float sgn = (dv < 64) ? -1.f : 1.f;
    int i0 = dv & 63;
    const float* ct = g_cos + t * 64 + i0;
    const float* st = g_sin + t * 64 + i0;

    uint4 qo, ko;
    const uint32_t* qav = (const uint32_t*)&qa;
    const uint32_t* qbv = (const uint32_t*)&qb;
    const uint32_t* kav = (const uint32_t*)&ka;
    const uint32_t* kbv = (const uint32_t*)&kb;
    uint32_t* qov = (uint32_t*)&qo;
    uint32_t* kov = (uint32_t*)&ko;
#pragma unroll
    for (int j = 0; j < 4; j++) {
        __half2 qah = *(const __half2*)&qav[j];
        __half2 qbh = *(const __half2*)&qbv[j];
        __half2 kah = *(const __half2*)&kav[j];
        __half2 kbh = *(const __half2*)&kbv[j];
        float c0 = ct[2 * j], c1 = ct[2 * j + 1];
        float s0 = st[2 * j], s1 = st[2 * j + 1];
        float q0 = __low2float(qah) * c0 + sgn * __low2float(qbh) * s0;
        float q1 = __high2float(qah) * c1 + sgn * __high2float(qbh) * s1;
        float k0 = __low2float(kah) * c0 + sgn * __low2float(kbh) * s0;
        float k1 = __high2float(kah) * c1 + sgn * __high2float(kbh) * s1;
        __half2 qh = __floats2half2_rn(q0, q1);
        __half2 kh = __floats2half2_rn(k0, k1);
        qov[j] = *(uint32_t*)&qh;
        kov[j] = *(uint32_t*)&kh;
    }

    size_t dst = ((size_t)bh * T_ + t) * D_ + dv;
    *(uint4*)&gq_s[dst] = qo;
    *(uint4*)&gk_s[dst] = ko;
}

// ---------------------------------------------------------------------------
// Flash attention (causal) on HMMA, fp16.  CTA = 64 q rows, 128 threads
// (4 warps x 16 rows), KV tile = 64 keys, 2-stage cp.async, smem 80 KB
// -> 2 CTAs/SM. Q fragments hoisted. Softmax in base-2 domain.
// V is read straight from g_qkv16 (row stride N3_).
// ---------------------------------------------------------------------------
#define KV_STG 32768                     // K 16K + V 16K
#define ATTN_SMEM (16384 + 2 * KV_STG)   // Q 16K + 2 KV stages = 80 KB

__device__ __forceinline__ void attn_load_kv(
    uint32_t skv, int stage,
    const __half* __restrict__ ks, const __half* __restrict__ vs,
    int k0, int tid)
{
    uint32_t st = skv + stage * KV_STG;
#pragma unroll
    for (int u = 0; u < 16; u++) {
        int idx = u * 128 + tid;
        int a = u >> 3;                     // 0=K (stride D_), 1=V (stride N3_)
        int rem = idx & 1023;
        int r = rem >> 4, c = rem & 15;
        uint32_t dst = st + a * 16384 + r * 256 + ((c ^ (r & 7)) << 4);
        if (a == 0)
            CP_ASYNC16(dst, ks + (size_t)(k0 + r) * D_ + c * 8);
        else
            CP_ASYNC16(dst, vs + (size_t)(k0 + r) * N3_ + c * 8);
    }
}

__global__ void __launch_bounds__(128, 2) attn_mma_kernel()
{
    extern __shared__ __align__(1024) char smem[];
    const uint32_t sb = smem_u32(smem);
    const int tid = threadIdx.x;
    const int w = tid >> 5, lane = tid & 31;     // 4 warps
    const int g = lane >> 2, tig = lane & 3;
    const int qt = (int)gridDim.x - 1 - (int)blockIdx.x;   // heavy tiles first
    const int bh = blockIdx.y;
    const int b = bh >> 4, h = bh & 15;
    const int q0 = qt * 64;
    const int NT = qt + 1;                                  // 64-key tiles

    const size_t hb = (size_t)bh * T_ * D_;
    const __half* Qs = gq_s + hb;
    const __half* Ks = gk_s + hb;
    const __half* Vs = g_qkv16 + (size_t)(b * T_) * N3_ + 2 * C_ + h * D_;

    const uint32_t sq = sb;
    const uint32_t skv = sb + 16384;

    // Load Q tile (64 rows); + KV stage 0 — one commit group
#pragma unroll
    for (int u = 0; u < 8; u++) {
        int idx = u * 128 + tid;
        int r = idx >> 4, c = idx & 15;
        uint32_t dst = sq + r * 256 + ((c ^ (r & 7)) << 4);
        CP_ASYNC16(dst, Qs + (size_t)(q0 + r) * D_ + c * 8);
    }
    attn_load_kv(skv, 0, Ks, Vs, 0, tid);
    CP_COMMIT();

    // Wait for Q + KV0, hoist Q fragments into registers (loop-invariant)
    CP_WAIT_GROUP(0);
    __syncthreads();
    uint32_t qf[8][4];
    {
        int qrow = w * 16 + (lane & 15);
#pragma unroll
        for (int ks = 0; ks < 8; ks++) {
            int qc = 2 * ks + (lane >> 4);
            uint32_t qa = sq + qrow * 256 + ((qc ^ (qrow & 7)) << 4);
            LDMATRIX_X4(qf[ks][0], qf[ks][1], qf[ks][2], qf[ks][3], qa);
        }
    }

    float O[16][4];
#pragma unroll
    for (int i = 0; i < 16; i++)
#pragma unroll
        for (int j = 0; j < 4; j++) O[i][j] = 0.f;
    float m0 = -1e30f, m1 = -1e30f, l0 = 0.f, l1 = 0.f;
    const float scale2 = 0.08838834764831845f * 1.4426950408889634f;
    const int row0 = q0 + w * 16 + g;
    const int row1 = row0 + 8;

    for (int kt = 0; kt < NT; kt++) {
        if (kt > 0) {
            CP_WAIT_GROUP(0);
            __syncthreads();
        }
        if (kt + 1 < NT)
            attn_load_kv(skv, (kt + 1) & 1, Ks, Vs, (kt + 1) * 64, tid);
        CP_COMMIT();
        const uint32_t sk = skv + (kt & 1) * KV_STG;

        // S = Q K^T  (64 q x 64 k)
        float S[8][4];
#pragma unroll
        for (int i = 0; i < 8; i++)
#pragma unroll
            for (int j = 0; j < 4; j++) S[i][j] = 0.f;

#pragma unroll
        for (int ks = 0; ks < 8; ks++) {
#pragma unroll
            for (int np = 0; np < 4; np++) {
                int kr = np * 16 + (lane & 7) + ((lane >> 4) << 3);
                int kc = 2 * ks + ((lane >> 3) & 1);
                uint32_t ka = sk + kr * 256 + ((kc ^ (kr & 7)) << 4);
                uint32_t kf[4];
                LDMATRIX_X4(kf[0], kf[1], kf[2], kf[3], ka);
                MMA_FP16(S[2 * np],     qf[ks], kf);
                MMA_FP16(S[2 * np + 1], qf[ks], kf + 2);
            }
        }

        // scale (base-2) + causal mask (diagonal tile only)
        const bool dom = (kt == qt);
#pragma unroll
        for (int nt = 0; nt < 8; nt++)
#pragma unroll
            for (int q = 0; q < 4; q++) {
                float v = S[nt][q] * scale2;
                if (dom) {
                    int col = kt * 64 + nt * 8 + 2 * tig + (q & 1);
                    int row = (q < 2) ? row0 : row1;
                    if (col > row) v = -1e30f;
                }
                S[nt][q] = v;
            }

        // online softmax (base-2)
        float mx0 = -1e30f, mx1 = -1e30f;
#pragma unroll
        for (int nt = 0; nt < 8; nt++) {
            mx0 = fmaxf(mx0, fmaxf(S[nt][0], S[nt][1]));
            mx1 = fmaxf(mx1, fmaxf(S[nt][2], S[nt][3]));
        }
        mx0 = fmaxf(mx0, __shfl_xor_sync(0xffffffffu, mx0, 1));
        mx0 = fmaxf(mx0, __shfl_xor_sync(0xffffffffu, mx0, 2));
        mx1 = fmaxf(mx1, __shfl_xor_sync(0xffffffffu, mx1, 1));
        mx1 = fmaxf(mx1, __shfl_xor_sync(0xffffffffu, mx1, 2));
        float mn0 = fmaxf(m0, mx0), mn1 = fmaxf(m1, mx1);
        float a0 = exp2f(m0 - mn0), a1 = exp2f(m1 - mn1);
        m0 = mn0; m1 = mn1;
        float s0 = 0.f, s1 = 0.f;
#pragma unroll
        for (int nt = 0; nt < 8; nt++) {
            S[nt][0] = exp2f(S[nt][0] - mn0); s0 += S[nt][0];
            S[nt][1] = exp2f(S[nt][1] - mn0); s0 += S[nt][1];
            S[nt][2] = exp2f(S[nt][2] - mn1); s1 += S[nt][2];
            S[nt][3] = exp2f(S[nt][3] - mn1); s1 += S[nt][3];
        }
        s0 += __shfl_xor_sync(0xffffffffu, s0, 1);
        s0 += __shfl_xor_sync(0xffffffffu, s0, 2);
        s1 += __shfl_xor_sync(0xffffffffu, s1, 1);
        s1 += __shfl_xor_sync(0xffffffffu, s1, 2);
        l0 = l0 * a0 + s0;
        l1 = l1 * a1 + s1;
#pragma unroll
        for (int nt = 0; nt < 16; nt++) {
            O[nt][0] *= a0; O[nt][1] *= a0;
            O[nt][2] *= a1; O[nt][3] *= a1;
        }

        // O += P V  (P fp16, V fp16; 64 keys)
#pragma unroll
        for (int j = 0; j < 4; j++) {
            uint32_t pa[4];
            {
                __half2 h2v;
                h2v = __floats2half2_rn(S[2 * j][0],     S[2 * j][1]);     pa[0] = *(uint32_t*)&h2v;
                h2v = __floats2half2_rn(S[2 * j][2],     S[2 * j][3]);     pa[1] = *(uint32_t*)&h2v;
                h2v = __floats2half2_rn(S[2 * j + 1][0], S[2 * j + 1][1]); pa[2] = *(uint32_t*)&h2v;
                h2v = __floats2half2_rn(S[2 * j + 1][2], S[2 * j + 1][3]); pa[3] = *(uint32_t*)&h2v;
            }
#pragma unroll
            for (int np = 0; np < 8; np++) {
                int vr = j * 16 + (lane & 15);
                int vc = 2 * np + (lane >> 4);
                uint32_t va = sk + 16384 + vr * 256 + ((vc ^ (vr & 7)) << 4);
                uint32_t vf[4];
                LDMATRIX_X4_T(vf[0], vf[1], vf[2], vf[3], va);
                MMA_FP16(O[2 * np],     pa, vf);
                MMA_FP16(O[2 * np + 1], pa, vf + 2);
            }
        }
    }

    // Epilogue: normalize, stage to smem (64 x 132 floats = 33 KB), write fp16
    __syncthreads();                          // all warps done with KV smem
    float li0 = 1.0f / l0, li1 = 1.0f / l1;
    float* stg = (float*)smem;
    {
        int r0l = w * 16 + g, r1l = r0l + 8;
#pragma unroll
        for (int nt = 0; nt < 16; nt++) {
            float2 v0 = make_float2(O[nt][0] * li0, O[nt][1] * li0);
            float2 v1 = make_float2(O[nt][2] * li1, O[nt][3] * li1);
            *(float2*)&stg[r0l * 132 + nt * 8 + 2 * tig] = v0;
            *(float2*)&stg[r1l * 132 + nt * 8 + 2 * tig] = v1;
        }
    }
    __syncthreads();
    {
        int r = tid >> 1, ch = (tid & 1) * 64;   // 64 rows, 128 threads
        size_t base = ((size_t)(b * T_ + q0 + r)) * C_ + h * 128 + ch;
#pragma unroll
        for (int c = 0; c < 64; c += 2) {
            float x = stg[r * 132 + ch + c], y = stg[r * 132 + ch + c + 1];
            *(__half2*)&gcx_s[base + c] = __floats2half2_rn(x, y);
        }
    }
}

// ---------------------------------------------------------------------------
extern "C" void kernel_launch(void* const* d_in, const int* in_sizes, int n_in,
                              void* d_out, int out_size)
{
    const float* x = nullptr; const float* w_qkv = nullptr;
    const float* w_proj = nullptr; const float* b_proj = nullptr;
    for (int i = 0; i < n_in; i++) {
        switch (in_sizes[i]) {
            case M_ * C_:  x      = (const float*)d_in[i]; break;
            case C_ * N3_: w_qkv  = (const float*)d_in[i]; break;
            case C_ * C_:  w_proj = (const float*)d_in[i]; break;
            case C_:       b_proj = (const float*)d_in[i]; break;
        }
    }
    float* out = (float*)d_out;

    void *p_qkv16, *p_x, *p_cx, *p_wq, *p_wp;
    cudaGetSymbolAddress(&p_qkv16, g_qkv16);
    cudaGetSymbolAddress(&p_x,   gx_s);
    cudaGetSymbolAddress(&p_cx,  gcx_s);
    cudaGetSymbolAddress(&p_wq,  gwq);
    cudaGetSymbolAddress(&p_wp,  gwp);

    cudaFuncSetAttribute(gemm_mma_kernel<0>,
                         cudaFuncAttributeMaxDynamicSharedMemorySize, GEMM_SMEM);
    cudaFuncSetAttribute(gemm_mma_kernel<1>,
                         cudaFuncAttributeMaxDynamicSharedMemorySize, GEMM_SMEM);
    cudaFuncSetAttribute(attn_mma_kernel,
                         cudaFuncAttributeMaxDynamicSharedMemorySize, ATTN_SMEM);

    // 1) fused operand prep (round + both transposes + rope table)
    prep_kernel<<<PREP_GRID, 256>>>(x, w_qkv, w_proj);

    // 2) QKV GEMM (HMMA fp16) -> fp16 output
    gemm_mma_kernel<1><<<dim3(N3_ / 128, M_ / 128), 256, GEMM_SMEM>>>(
        (const __half*)p_x, (const __half*)p_wq,
        nullptr, (__half*)p_qkv16, nullptr, N3_, C_);

    // 3) RoPE (q/k only) -> fp16 [BH,T,D]
    rope_kernel<<<(BH_ * T_ * 16) / 256, 256>>>();

    // 4) causal flash attention (V read directly from g_qkv16)
    attn_mma_kernel<<<dim3(T_ / 64, BH_), 128, ATTN_SMEM>>>();

    // 5) projection GEMM (HMMA fp16) + bias -> fp32 out
    gemm_mma_kernel<0><<<dim3(C_ / 128, M_ / 128), 256, GEMM_SMEM>>>(
        (const __half*)p_cx, (const __half*)p_wp,
        out, nullptr, b_proj, C_, C_);
}

// round 17
// speedup vs baseline: 1.1888x; 1.0254x over previous
#include <cuda_runtime.h>
#include <cuda_bf16.h>
#include <cuda_fp16.h>
#include <math.h>
#include <stdint.h>

// Problem constants
#define B_   4
#define T_   2048
#define C_   2048
#define H_   16
#define D_   128
#define BH_  (B_ * H_)        // 64
#define M_   (B_ * T_)        // 8192
#define N3_  (3 * C_)         // 6144

// ============================ helpers ======================================
__device__ __forceinline__ uint32_t smem_u32(const void* p) {
    uint32_t a;
    asm("{ .reg .u64 t; cvta.to.shared.u64 t, %1; cvt.u32.u64 %0, t; }"
        : "=r"(a) : "l"(p));
    return a;
}
#define CP_ASYNC16(saddr, gptr) \
    asm volatile("cp.async.cg.shared.global [%0], [%1], 16;" \
                 :: "r"(saddr), "l"(gptr) : "memory")
#define CP_COMMIT() asm volatile("cp.async.commit_group;" ::: "memory")
#define CP_WAIT_GROUP(n) asm volatile("cp.async.wait_group %0;" :: "n"(n) : "memory")

#define LDMATRIX_X4(r0, r1, r2, r3, addr) \
    asm volatile("ldmatrix.sync.aligned.m8n8.x4.shared.b16 {%0,%1,%2,%3}, [%4];" \
                 : "=r"(r0), "=r"(r1), "=r"(r2), "=r"(r3) : "r"(addr))
#define LDMATRIX_X4_T(r0, r1, r2, r3, addr) \
    asm volatile("ldmatrix.sync.aligned.m8n8.x4.trans.shared.b16 {%0,%1,%2,%3}, [%4];" \
                 : "=r"(r0), "=r"(r1), "=r"(r2), "=r"(r3) : "r"(addr))
#define MMA_FP16(c, a, b) \
    asm volatile("mma.sync.aligned.m16n8k16.row.col.f32.f16.f16.f32 " \
                 "{%0,%1,%2,%3}, {%4,%5,%6,%7}, {%8,%9}, {%0,%1,%2,%3};" \
                 : "+f"((c)[0]), "+f"((c)[1]), "+f"((c)[2]), "+f"((c)[3]) \
                 : "r"((a)[0]), "r"((a)[1]), "r"((a)[2]), "r"((a)[3]), \
                   "r"((b)[0]), "r"((b)[1]))

// ---------------- scratch (device globals; no allocation allowed) ----------
__device__ __half g_qkv16[M_ * N3_];       // [8192, 6144] fp16 (QKV pre-rope)
__device__ float g_cos[T_ * 64];
__device__ float g_sin[T_ * 64];
__device__ __half gx_s[M_ * C_];           // activations [M,K]
__device__ __half gcx_s[M_ * C_];          // ctx [M,K]
__device__ __half gwq[N3_ * C_];           // W_qkv^T [N,K]
__device__ __half gwp[C_ * C_];            // W_proj^T [N,K]
__device__ __half gq_s[BH_ * T_ * D_];
__device__ __half gk_s[BH_ * T_ * D_];
// V is read directly from g_qkv16 (no rope needed) — no gv buffer.

// ---------------------------------------------------------------------------
// Fused prep: one launch dispatching four independent workloads by blockIdx.
//  [0, 16384)       : round x fp32 -> gx_s fp16 (float4 per thread)
//  [16384, 28672)   : transpose+round w_qkv -> gwq  (12288 tiles of 32x32)
//  [28672, 32768)   : transpose+round w_proj -> gwp (4096 tiles)
//  [32768, 33280)   : RoPE cos/sin table
// ---------------------------------------------------------------------------
#define PREP_GRID 33280

__global__ void __launch_bounds__(256) prep_kernel(
    const float* __restrict__ x, const float* __restrict__ wqv,
    const float* __restrict__ wpr)
{
    __shared__ float t[32][33];
    const int bid = blockIdx.x;
    const int tid = threadIdx.x;

    if (bid < 16384) {
        int i = bid * 256 + tid;                 // exactly covers M_*C_/4
        float4 v = ((const float4*)x)[i];
        __half2* hp = (__half2*)gx_s;
        hp[i * 2 + 0] = __floats2half2_rn(v.x, v.y);
        hp[i * 2 + 1] = __floats2half2_rn(v.z, v.w);
    } else if (bid < 32768) {
        const float* W; __half* Th; int N; int idx;
        if (bid < 28672) { W = wqv; Th = gwq; N = N3_; idx = bid - 16384; }
        else             { W = wpr; Th = gwp; N = C_;  idx = bid - 28672; }
        const int K = C_;
        const int ntx = N / 32;
        const int bn = (idx % ntx) * 32;
        const int bk = (idx / ntx) * 32;
        const int xx = tid & 31, yy = tid >> 5;   // 32 x 8
#pragma unroll
        for (int i = 0; i < 32; i += 8)
            t[yy + i][xx] = W[(size_t)(bk + yy + i) * N + bn + xx];
        __syncthreads();
#pragma unroll
        for (int i = 0; i < 32; i += 8) {
            float v = t[xx][yy + i];
            Th[(size_t)(bn + yy + i) * K + bk + xx] = __float2half_rn(v);
        }
    } else {
        int g = (bid - 32768) * 256 + tid;
        if (g < T_ * 64) {
            int tt = g >> 6, ii = g & 63;
            double invf = pow(10000.0, -(double)ii / 64.0);
            float  angf = (float)tt * (float)invf;
            double ang  = (double)angf;
            g_cos[g] = (float)cos(ang);
            g_sin[g] = (float)sin(ang);
        }
    }
}

// ---------------------------------------------------------------------------
// HMMA GEMM: C[M,N] = A[M,K] @ B[N,K]^T, plain fp16 x fp16, fp32 accum.
// CTA 128x128, BK=64, 3-stage cp.async (wait_group 1), 8 warps, 2 CTAs/SM.
// OUT16=0: fp32 epilogue (+bias). OUT16=1: fp16 epilogue (no bias).
// NOTE: unconditional CP_COMMIT per iteration is load-bearing for the
// wait_group(1) accounting. Kernel is at the 128-reg limit — do not add state.
// ---------------------------------------------------------------------------
#define STG_BYTES 32768              // A 16K + B 16K
#define OFF_A 0
#define OFF_B 16384
#define GEMM_SMEM (3 * STG_BYTES)    // 96 KB

__device__ __forceinline__ void gemm_load_stage(
    uint32_t sb, int stage,
    const __half* __restrict__ A, const __half* __restrict__ Bh,
    int row0, int col0, int kb, int K, int tid)
{
    uint32_t st = sb + stage * STG_BYTES;
    const int k0 = kb * 64;
#pragma unroll
    for (int u = 0; u < 4; u++) {
        int idx = u * 256 + tid;                 // 1024 16B chunks per operand
        int r = idx >> 3, c = idx & 7;
        uint32_t sw = (uint32_t)(r * 128 + ((c ^ (r & 7)) << 4));
        size_t ga = (size_t)(row0 + r) * K + k0 + c * 8;
        size_t gb = (size_t)(col0 + r) * K + k0 + c * 8;
        CP_ASYNC16(st + OFF_A + sw, A + ga);
        CP_ASYNC16(st + OFF_B + sw, Bh + gb);
    }
}

template<int OUT16>
__global__ void __launch_bounds__(256, 2) gemm_mma_kernel(
    const __half* __restrict__ A, const __half* __restrict__ Bh,
    float* __restrict__ Cout, __half* __restrict__ Cout16,
    const float* __restrict__ bias, int N, int K)
{
    extern __shared__ __align__(1024) char smem[];
    const uint32_t sb = smem_u32(smem);
    const int tid = threadIdx.x;
    const int wid = tid >> 5, lane = tid & 31;
    const int wr = wid >> 2, wc = wid & 3;       // warp grid 2 x 4
    const int col0 = blockIdx.x * 128;
    const int row0 = blockIdx.y * 128;
    const int NK = K / 64;

    float acc[4][4][4];
#pragma unroll
    for (int i = 0; i < 4; i++)
#pragma unroll
        for (int j = 0; j < 4; j++)
#pragma unroll
            for (int k = 0; k < 4; k++) acc[i][j][k] = 0.f;

    gemm_load_stage(sb, 0, A, Bh, row0, col0, 0, K, tid);
    CP_COMMIT();
    gemm_load_stage(sb, 1, A, Bh, row0, col0, 1, K, tid);
    CP_COMMIT();

    const int a_row = wr * 64 + (lane & 15);
    const int a_cg  = (lane >> 4);
    const int b_row = wc * 32 + (lane & 7) + ((lane >> 4) << 3);
    const int b_cg  = ((lane >> 3) & 1);

    int slot = 0, nslot = 2;
    for (int kb = 0; kb < NK; kb++) {
        CP_WAIT_GROUP(1);
        __syncthreads();
        if (kb + 2 < NK)
            gemm_load_stage(sb, nslot, A, Bh, row0, col0, kb + 2, K, tid);
        CP_COMMIT();

        uint32_t st = sb + slot * STG_BYTES;
#pragma unroll
        for (int ks = 0; ks < 4; ks++) {
            uint32_t af[4][4], bf[4][2];
#pragma unroll
            for (int mt = 0; mt < 4; mt++) {
                int r = a_row + mt * 16;
                int c = ks * 2 + a_cg;
                uint32_t ad = st + (uint32_t)(r * 128 + ((c ^ (r & 7)) << 4));
                LDMATRIX_X4(af[mt][0], af[mt][1], af[mt][2], af[mt][3], ad + OFF_A);
            }
#pragma unroll
            for (int ntp = 0; ntp < 2; ntp++) {
                int n = b_row + ntp * 16;
                int c = ks * 2 + b_cg;
                uint32_t bd = st + (uint32_t)(n * 128 + ((c ^ (n & 7)) << 4));
                LDMATRIX_X4(bf[2 * ntp][0], bf[2 * ntp][1],
                            bf[2 * ntp + 1][0], bf[2 * ntp + 1][1], bd + OFF_B);
            }
#pragma unroll
            for (int mt = 0; mt < 4; mt++)
#pragma unroll
                for (int nt = 0; nt < 4; nt++)
                    MMA_FP16(acc[mt][nt], af[mt], bf[nt]);
        }
        slot = (slot == 2) ? 0 : slot + 1;
        nslot = (nslot == 2) ? 0 : nslot + 1;
    }

    const int er = lane >> 2;
    const int ec = (lane & 3) * 2;
#pragma unroll
    for (int mt = 0; mt < 4; mt++) {
        int row = row0 + wr * 64 + mt * 16 + er;
#pragma unroll
        for (int nt = 0; nt < 4; nt++) {
            int col = col0 + wc * 32 + nt * 8 + ec;
            if (OUT16) {
                *(__half2*)&Cout16[(size_t)row * N + col] =
                    __floats2half2_rn(acc[mt][nt][0], acc[mt][nt][1]);
                *(__half2*)&Cout16[(size_t)(row + 8) * N + col] =
                    __floats2half2_rn(acc[mt][nt][2], acc[mt][nt][3]);
            } else {
                float b0 = 0.f, b1 = 0.f;
                if (bias) { b0 = bias[col]; b1 = bias[col + 1]; }
                float2 v0, v1;
                v0.x = acc[mt][nt][0] + b0; v0.y = acc[mt][nt][1] + b1;
                v1.x = acc[mt][nt][2] + b0; v1.y = acc[mt][nt][3] + b1;
                *(float2*)&Cout[(size_t)row * N + col] = v0;
                *(float2*)&Cout[(size_t)(row + 8) * N + col] = v1;
            }
        }
    }
}

// ---------------------------------------------------------------------------
// RoPE (vectorized, q/k only): g_qkv16[B,T,3C] -> q/k fp16 [BH,T,D]
// ---------------------------------------------------------------------------
__global__ void __launch_bounds__(256) rope_kernel()
{
    int g = blockIdx.x * 256 + threadIdx.x;     // BH*T*16 threads
    int dv = (g & 15) * 8;                      // 0,8,...,120
    int t  = (g >> 4) & 2047;
    int bh = g >> 15;
    int b  = bh >> 4, h = bh & 15;

    size_t src  = ((size_t)(b * T_ + t)) * N3_ + h * D_ + dv;
    size_t srcp = src - dv + (dv ^ 64);

    uint4 qa = *(const uint4*)&g_qkv16[src];
    uint4 qb = *(const uint4*)&g_qkv16[srcp];
    uint4 ka = *(const uint4*)&g_qkv16[src + C_];
    uint4 kb = *(const uint4*)&g_qkv16[srcp + C_];

    float sgn = (dv < 64) ? -1.f : 1.f;
    int i0 = dv & 63;
    const float* ct = g_cos + t * 64 + i0;
    const float* st = g_sin + t * 64 + i0;

    uint4 qo, ko;
    const uint32_t* qav = (const uint32_t*)&qa;
    const uint32_t* qbv = (const uint32_t*)&qb;
    const uint32_t* kav = (const uint32_t*)&ka;
    const uint32_t* kbv = (const uint32_t*)&kb;
    uint32_t* qov = (uint32_t*)&qo;
    uint32_t* kov = (uint32_t*)&ko;
#pragma unroll
    for (int j = 0; j < 4; j++) {
        __half2 qah = *(const __half2*)&qav[j];
        __half2 qbh = *(const __half2*)&qbv[j];
        __half2 kah = *(const __half2*)&kav[j];
        __half2 kbh = *(const __half2*)&kbv[j];
        float c0 = ct[2 * j], c1 = ct[2 * j + 1];
        float s0 = st[2 * j], s1 = st[2 * j + 1];
        float q0 = __low2float(qah) * c0 + sgn * __low2float(qbh) * s0;
        float q1 = __high2float(qah) * c1 + sgn * __high2float(qbh) * s1;
        float k0 = __low2float(kah) * c0 + sgn * __low2float(kbh) * s0;
        float k1 = __high2float(kah) * c1 + sgn * __high2float(kbh) * s1;
        __half2 qh = __floats2half2_rn(q0, q1);
        __half2 kh = __floats2half2_rn(k0, k1);
        qov[j] = *(uint32_t*)&qh;
        kov[j] = *(uint32_t*)&kh;
    }

    size_t dst = ((size_t)bh * T_ + t) * D_ + dv;
    *(uint4*)&gq_s[dst] = qo;
    *(uint4*)&gk_s[dst] = ko;
}

// ---------------------------------------------------------------------------
// Flash attention (causal) on HMMA, fp16.  CTA = 64 q rows, 128 threads
// (4 warps x 16 rows), KV tile = 64 keys, 2-stage cp.async, smem 80 KB
// -> 2 CTAs/SM. Q fragments hoisted. Softmax in base-2 domain.
// Grid = (bh, qt-slot): y-major dispatch gives GLOBAL heavy-first (LPT) order.
// ---------------------------------------------------------------------------
#define KV_STG 32768                     // K 16K + V 16K
#define ATTN_SMEM (16384 + 2 * KV_STG)   // Q 16K + 2 KV stages = 80 KB

__device__ __forceinline__ void attn_load_kv(
    uint32_t skv, int stage,
    const __half* __restrict__ ks, const __half* __restrict__ vs,
    int k0, int tid)
{
    uint32_t st = skv + stage * KV_STG;
#pragma unroll
    for (int u = 0; u < 16; u++) {
        int idx = u * 128 + tid;
        int a = u >> 3;                     // 0=K (stride D_), 1=V (stride N3_)
        int rem = idx & 1023;
        int r = rem >> 4, c = rem & 15;
        uint32_t dst = st + a * 16384 + r * 256 + ((c ^ (r & 7)) << 4);
        if (a == 0)
            CP_ASYNC16(dst, ks + (size_t)(k0 + r) * D_ + c * 8);
        else
            CP_ASYNC16(dst, vs + (size_t)(k0 + r) * N3_ + c * 8);
    }
}

__global__ void __launch_bounds__(128, 2) attn_mma_kernel()
{
    extern __shared__ __align__(1024) char smem[];
    const uint32_t sb = smem_u32(smem);
    const int tid = threadIdx.x;
    const int w = tid >> 5, lane = tid & 31;     // 4 warps
    const int g = lane >> 2, tig = lane & 3;
    const int qt = (int)gridDim.y - 1 - (int)blockIdx.y;   // global heavy-first
    const int bh = blockIdx.x;
    const int b = bh >> 4, h = bh & 15;
    const int q0 = qt * 64;
    const int NT = qt + 1;                                  // 64-key tiles

    const size_t hb = (size_t)bh * T_ * D_;
    const __half* Qs = gq_s + hb;
    const __half* Ks = gk_s + hb;
    const __half* Vs = g_qkv16 + (size_t)(b * T_) * N3_ + 2 * C_ + h * D_;

    const uint32_t sq = sb;
    const uint32_t skv = sb + 16384;

    // Load Q tile (64 rows); + KV stage 0 — one commit group
#pragma unroll
    for (int u = 0; u < 8; u++) {
        int idx = u * 128 + tid;
        int r = idx >> 4, c = idx & 15;
        uint32_t dst = sq + r * 256 + ((c ^ (r & 7)) << 4);
        CP_ASYNC16(dst, Qs + (size_t)(q0 + r) * D_ + c * 8);
    }
    attn_load_kv(skv, 0, Ks, Vs, 0, tid);
    CP_COMMIT();

    // Wait for Q + KV0, hoist Q fragments into registers (loop-invariant)
    CP_WAIT_GROUP(0);
    __syncthreads();
    uint32_t qf[8][4];
    {
        int qrow = w * 16 + (lane & 15);
#pragma unroll
        for (int ks = 0; ks < 8; ks++) {
            int qc = 2 * ks + (lane >> 4);
            uint32_t qa = sq + qrow * 256 + ((qc ^ (qrow & 7)) << 4);
            LDMATRIX_X4(qf[ks][0], qf[ks][1], qf[ks][2], qf[ks][3], qa);
        }
    }

    float O[16][4];
#pragma unroll
    for (int i = 0; i < 16; i++)
#pragma unroll
        for (int j = 0; j < 4; j++) O[i][j] = 0.f;
    float m0 = -1e30f, m1 = -1e30f, l0 = 0.f, l1 = 0.f;
    const float scale2 = 0.08838834764831845f * 1.4426950408889634f;
    const int row0 = q0 + w * 16 + g;
    const int row1 = row0 + 8;

    for (int kt = 0; kt < NT; kt++) {
        if (kt > 0) {
            CP_WAIT_GROUP(0);
            __syncthreads();
        }
        if (kt + 1 < NT)
            attn_load_kv(skv, (kt + 1) & 1, Ks, Vs, (kt + 1) * 64, tid);
        CP_COMMIT();
        const uint32_t sk = skv + (kt & 1) * KV_STG;

        // S = Q K^T  (64 q x 64 k)
        float S[8][4];
#pragma unroll
        for (int i = 0; i < 8; i++)
#pragma unroll
            for (int j = 0; j < 4; j++) S[i][j] = 0.f;

#pragma unroll
        for (int ks = 0; ks < 8; ks++) {
#pragma unroll
            for (int np = 0; np < 4; np++) {
                int kr = np * 16 + (lane & 7) + ((lane >> 4) << 3);
                int kc = 2 * ks + ((lane >> 3) & 1);
                uint32_t ka = sk + kr * 256 + ((kc ^ (kr & 7)) << 4);
                uint32_t kf[4];
                LDMATRIX_X4(kf[0], kf[1], kf[2], kf[3], ka);
                MMA_FP16(S[2 * np],     qf[ks], kf);
                MMA_FP16(S[2 * np + 1], qf[ks], kf + 2);
            }
        }

        // scale (base-2) + causal mask (diagonal tile only)
        const bool dom = (kt == qt);
#pragma unroll
        for (int nt = 0; nt < 8; nt++)
#pragma unroll
            for (int q = 0; q < 4; q++) {
                float v = S[nt][q] * scale2;
                if (dom) {
                    int col = kt * 64 + nt * 8 + 2 * tig + (q & 1);
                    int row = (q < 2) ? row0 : row1;
                    if (col > row) v = -1e30f;
                }
                S[nt][q] = v;
            }

        // online softmax (base-2)
        float mx0 = -1e30f, mx1 = -1e30f;
#pragma unroll
        for (int nt = 0; nt < 8; nt++) {
            mx0 = fmaxf(mx0, fmaxf(S[nt][0], S[nt][1]));
            mx1 = fmaxf(mx1, fmaxf(S[nt][2], S[nt][3]));
        }
        mx0 = fmaxf(mx0, __shfl_xor_sync(0xffffffffu, mx0, 1));
        mx0 = fmaxf(mx0, __shfl_xor_sync(0xffffffffu, mx0, 2));
        mx1 = fmaxf(mx1, __shfl_xor_sync(0xffffffffu, mx1, 1));
        mx1 = fmaxf(mx1, __shfl_xor_sync(0xffffffffu, mx1, 2));
        float mn0 = fmaxf(m0, mx0), mn1 = fmaxf(m1, mx1);
        float a0 = exp2f(m0 - mn0), a1 = exp2f(m1 - mn1);
        m0 = mn0; m1 = mn1;
        float s0 = 0.f, s1 = 0.f;
#pragma unroll
        for (int nt = 0; nt < 8; nt++) {
            S[nt][0] = exp2f(S[nt][0] - mn0); s0 += S[nt][0];
            S[nt][1] = exp2f(S[nt][1] - mn0); s0 += S[nt][1];
            S[nt][2] = exp2f(S[nt][2] - mn1); s1 += S[nt][2];
            S[nt][3] = exp2f(S[nt][3] - mn1); s1 += S[nt][3];
        }
        s0 += __shfl_xor_sync(0xffffffffu, s0, 1);
        s0 += __shfl_xor_sync(0xffffffffu, s0, 2);
        s1 += __shfl_xor_sync(0xffffffffu, s1, 1);
        s1 += __shfl_xor_sync(0xffffffffu, s1, 2);
        l0 = l0 * a0 + s0;
        l1 = l1 * a1 + s1;
#pragma unroll
        for (int nt = 0; nt < 16; nt++) {
            O[nt][0] *= a0; O[nt][1] *= a0;
            O[nt][2] *= a1; O[nt][3] *= a1;
        }

        // O += P V  (P fp16, V fp16; 64 keys)
#pragma unroll
        for (int j = 0; j < 4; j++) {
            uint32_t pa[4];
            {
                __half2 h2v;
                h2v = __floats2half2_rn(S[2 * j][0],     S[2 * j][1]);     pa[0] = *(uint32_t*)&h2v;
                h2v = __floats2half2_rn(S[2 * j][2],     S[2 * j][3]);     pa[1] = *(uint32_t*)&h2v;
                h2v = __floats2half2_rn(S[2 * j + 1][0], S[2 * j + 1][1]); pa[2] = *(uint32_t*)&h2v;
                h2v = __floats2half2_rn(S[2 * j + 1][2], S[2 * j + 1][3]); pa[3] = *(uint32_t*)&h2v;
            }
#pragma unroll
            for (int np = 0; np < 8; np++) {
                int vr = j * 16 + (lane & 15);
                int vc = 2 * np + (lane >> 4);
                uint32_t va = sk + 16384 + vr * 256 + ((vc ^ (vr & 7)) << 4);
                uint32_t vf[4];
                LDMATRIX_X4_T(vf[0], vf[1], vf[2], vf[3], va);
                MMA_FP16(O[2 * np],     pa, vf);
                MMA_FP16(O[2 * np + 1], pa, vf + 2);
            }
        }
    }

    // Epilogue: normalize, stage to smem (64 x 132 floats = 33 KB), write fp16
    __syncthreads();                          // all warps done with KV smem
    float li0 = 1.0f / l0, li1 = 1.0f / l1;
    float* stg = (float*)smem;
    {
        int r0l = w * 16 + g, r1l = r0l + 8;
#pragma unroll
        for (int nt = 0; nt < 16; nt++) {
            float2 v0 = make_float2(O[nt][0] * li0, O[nt][1] * li0);
            float2 v1 = make_float2(O[nt][2] * li1, O[nt][3] * li1);
            *(float2*)&stg[r0l * 132 + nt * 8 + 2 * tig] = v0;
            *(float2*)&stg[r1l * 132 + nt * 8 + 2 * tig] = v1;
        }
    }
    __syncthreads();
    {
        int r = tid >> 1, ch = (tid & 1) * 64;   // 64 rows, 128 threads
        size_t base = ((size_t)(b * T_ + q0 + r)) * C_ + h * 128 + ch;
#pragma unroll
        for (int c = 0; c < 64; c += 2) {
            float x = stg[r * 132 + ch + c], y = stg[r * 132 + ch + c + 1];
            *(__half2*)&gcx_s[base + c] = __floats2half2_rn(x, y);
        }
    }
}

// ---------------------------------------------------------------------------
extern "C" void kernel_launch(void* const* d_in, const int* in_sizes, int n_in,
                              void* d_out, int out_size)
{
    const float* x = nullptr; const float* w_qkv = nullptr;
    const float* w_proj = nullptr; const float* b_proj = nullptr;
    for (int i = 0; i < n_in; i++) {
        switch (in_sizes[i]) {
            case M_ * C_:  x      = (const float*)d_in[i]; break;
            case C_ * N3_: w_qkv  = (const float*)d_in[i]; break;
            case C_ * C_:  w_proj = (const float*)d_in[i]; break;
            case C_:       b_proj = (const float*)d_in[i]; break;
        }
    }
    float* out = (float*)d_out;

    void *p_qkv16, *p_x, *p_cx, *p_wq, *p_wp;
    cudaGetSymbolAddress(&p_qkv16, g_qkv16);
    cudaGetSymbolAddress(&p_x,   gx_s);
    cudaGetSymbolAddress(&p_cx,  gcx_s);
    cudaGetSymbolAddress(&p_wq,  gwq);
    cudaGetSymbolAddress(&p_wp,  gwp);

    cudaFuncSetAttribute(gemm_mma_kernel<0>,
                         cudaFuncAttributeMaxDynamicSharedMemorySize, GEMM_SMEM);
    cudaFuncSetAttribute(gemm_mma_kernel<1>,
                         cudaFuncAttributeMaxDynamicSharedMemorySize, GEMM_SMEM);
    cudaFuncSetAttribute(attn_mma_kernel,
                         cudaFuncAttributeMaxDynamicSharedMemorySize, ATTN_SMEM);

    // 1) fused operand prep (round + both transposes + rope table)
    prep_kernel<<<PREP_GRID, 256>>>(x, w_qkv, w_proj);

    // 2) QKV GEMM (HMMA fp16) -> fp16 output
    gemm_mma_kernel<1><<<dim3(N3_ / 128, M_ / 128), 256, GEMM_SMEM>>>(
        (const __half*)p_x, (const __half*)p_wq,
        nullptr, (__half*)p_qkv16, nullptr, N3_, C_);

    // 3) RoPE (q/k only) -> fp16 [BH,T,D]
    rope_kernel<<<(BH_ * T_ * 16) / 256, 256>>>();

    // 4) causal flash attention — grid (bh, qt-slot) for global heavy-first
    attn_mma_kernel<<<dim3(BH_, T_ / 64), 128, ATTN_SMEM>>>();

    // 5) projection GEMM (HMMA fp16) + bias -> fp32 out
    gemm_mma_kernel<0><<<dim3(C_ / 128, M_ / 128), 256, GEMM_SMEM>>>(
        (const __half*)p_cx, (const __half*)p_wp,
        out, nullptr, b_proj, C_, C_);
}